// round 1
// baseline (speedup 1.0000x reference)
#include <cuda_runtime.h>
#include <math.h>
#include <stdint.h>

// Problem dims (fixed)
#define BB 2
#define TT 2048
#define DD 2048
#define HHN 16
#define KKD 128
#define VVD 128
#define BT  (BB*TT)     // 4096
#define HK  (HHN*KKD)   // 2048

// Scratch (device globals: no allocation allowed)
__device__ float g_q[BT*HK];
__device__ float g_k[BT*HK];
__device__ float g_v[BT*HK];
__device__ float g_alpha[BT*HHN];
__device__ float g_beta[BT*HHN];

__device__ __forceinline__ float to_tf32(float x) {
    asm("cvt.rna.tf32.f32 %0, %0;" : "+f"(x));
    return x;
}

__device__ __forceinline__ void mma_tf32(float* d, const uint32_t* a, const uint32_t* b) {
    asm volatile("mma.sync.aligned.m16n8k8.row.col.f32.tf32.tf32.f32 "
        "{%0,%1,%2,%3}, {%4,%5,%6,%7}, {%8,%9}, {%0,%1,%2,%3};"
        : "+f"(d[0]), "+f"(d[1]), "+f"(d[2]), "+f"(d[3])
        : "r"(a[0]), "r"(a[1]), "r"(a[2]), "r"(a[3]), "r"(b[0]), "r"(b[1]));
}

// ---------------------------------------------------------------------------
// Projection GEMM: C[4096,2048] = X[4096,2048] * W^T  (W is [2048,2048], row-major)
// tf32 mma.sync, BM=BN=128, BK=16, 256 threads, 8 warps (4x2), warp tile 32x64.
// Smem row stride 20 floats -> conflict-free fragment LDS.
// ---------------------------------------------------------------------------
#define SSTR 20

__global__ __launch_bounds__(256)
void gdn_proj_gemm(const float* __restrict__ X,
                   const float* __restrict__ Wq,
                   const float* __restrict__ Wk,
                   const float* __restrict__ Wv) {
    const float* W; float* C;
    if (blockIdx.z == 0)      { W = Wq; C = g_q; }
    else if (blockIdx.z == 1) { W = Wk; C = g_k; }
    else                      { W = Wv; C = g_v; }

    __shared__ float As[128*SSTR];
    __shared__ float Bs[128*SSTR];

    const int tid  = threadIdx.x;
    const int lane = tid & 31;
    const int wid  = tid >> 5;
    const int wm   = wid >> 1;      // 0..3
    const int wn   = wid & 1;       // 0..1
    const int g    = lane >> 2;     // 0..7
    const int tig  = lane & 3;      // 0..3

    const int rowA = blockIdx.y * 128;   // M tile (bt rows)
    const int rowB = blockIdx.x * 128;   // N tile (output feature rows of W)

    // global->smem load mapping: 512 float4 per tile, 2 per thread
    const int r0 = tid >> 2;             // 0..63
    const int r1 = r0 + 64;              // 64..127
    const int c0 = (tid & 3) * 4;        // 0,4,8,12

    float acc[2][8][4];
    #pragma unroll
    for (int i = 0; i < 2; i++)
        #pragma unroll
        for (int j = 0; j < 8; j++)
            #pragma unroll
            for (int l = 0; l < 4; l++) acc[i][j][l] = 0.f;

    float4 pa0, pa1, pb0, pb1;
    pa0 = *(const float4*)(X + (size_t)(rowA + r0)*DD + c0);
    pa1 = *(const float4*)(X + (size_t)(rowA + r1)*DD + c0);
    pb0 = *(const float4*)(W + (size_t)(rowB + r0)*DD + c0);
    pb1 = *(const float4*)(W + (size_t)(rowB + r1)*DD + c0);

    const int KT = DD / 16;   // 128
    for (int kt = 0; kt < KT; ++kt) {
        // store prefetched tile to smem (tf32-rounded)
        As[r0*SSTR + c0 + 0] = to_tf32(pa0.x);
        As[r0*SSTR + c0 + 1] = to_tf32(pa0.y);
        As[r0*SSTR + c0 + 2] = to_tf32(pa0.z);
        As[r0*SSTR + c0 + 3] = to_tf32(pa0.w);
        As[r1*SSTR + c0 + 0] = to_tf32(pa1.x);
        As[r1*SSTR + c0 + 1] = to_tf32(pa1.y);
        As[r1*SSTR + c0 + 2] = to_tf32(pa1.z);
        As[r1*SSTR + c0 + 3] = to_tf32(pa1.w);
        Bs[r0*SSTR + c0 + 0] = to_tf32(pb0.x);
        Bs[r0*SSTR + c0 + 1] = to_tf32(pb0.y);
        Bs[r0*SSTR + c0 + 2] = to_tf32(pb0.z);
        Bs[r0*SSTR + c0 + 3] = to_tf32(pb0.w);
        Bs[r1*SSTR + c0 + 0] = to_tf32(pb1.x);
        Bs[r1*SSTR + c0 + 1] = to_tf32(pb1.y);
        Bs[r1*SSTR + c0 + 2] = to_tf32(pb1.z);
        Bs[r1*SSTR + c0 + 3] = to_tf32(pb1.w);
        __syncthreads();

        // prefetch next tile (global) -- latency hidden by compute below
        if (kt + 1 < KT) {
            const int k0 = (kt + 1) * 16;
            pa0 = *(const float4*)(X + (size_t)(rowA + r0)*DD + k0 + c0);
            pa1 = *(const float4*)(X + (size_t)(rowA + r1)*DD + k0 + c0);
            pb0 = *(const float4*)(W + (size_t)(rowB + r0)*DD + k0 + c0);
            pb1 = *(const float4*)(W + (size_t)(rowB + r1)*DD + k0 + c0);
        }

        #pragma unroll
        for (int kk = 0; kk < 16; kk += 8) {
            uint32_t afr[2][4], bfr[8][2];
            #pragma unroll
            for (int mt = 0; mt < 2; mt++) {
                const int rb = wm*32 + mt*16;
                afr[mt][0] = __float_as_uint(As[(rb + g    )*SSTR + kk + tig    ]);
                afr[mt][1] = __float_as_uint(As[(rb + g + 8)*SSTR + kk + tig    ]);
                afr[mt][2] = __float_as_uint(As[(rb + g    )*SSTR + kk + tig + 4]);
                afr[mt][3] = __float_as_uint(As[(rb + g + 8)*SSTR + kk + tig + 4]);
            }
            #pragma unroll
            for (int nt = 0; nt < 8; nt++) {
                const int cb = wn*64 + nt*8;
                bfr[nt][0] = __float_as_uint(Bs[(cb + g)*SSTR + kk + tig    ]);
                bfr[nt][1] = __float_as_uint(Bs[(cb + g)*SSTR + kk + tig + 4]);
            }
            #pragma unroll
            for (int mt = 0; mt < 2; mt++)
                #pragma unroll
                for (int nt = 0; nt < 8; nt++)
                    mma_tf32(acc[mt][nt], afr[mt], bfr[nt]);
        }
        __syncthreads();
    }

    // epilogue
    #pragma unroll
    for (int mt = 0; mt < 2; mt++) {
        #pragma unroll
        for (int nt = 0; nt < 8; nt++) {
            const int r  = rowA + wm*32 + mt*16 + g;
            const int cc = rowB + wn*64 + nt*8 + tig*2;
            *(float2*)(C + (size_t)r*HK + cc)       = make_float2(acc[mt][nt][0], acc[mt][nt][1]);
            *(float2*)(C + (size_t)(r + 8)*HK + cc) = make_float2(acc[mt][nt][2], acc[mt][nt][3]);
        }
    }
}

// ---------------------------------------------------------------------------
// alpha/beta: [4096,32] = X @ [Wa;Wb]^T, then sigmoid / softplus*K^-0.5.
// 64-row M blocks, 256 threads; thread owns (col c, 8 rows).
// ---------------------------------------------------------------------------
__global__ __launch_bounds__(256)
void gdn_ab_kernel(const float* __restrict__ X,
                   const float* __restrict__ Wa, const float* __restrict__ ba,
                   const float* __restrict__ Wb, const float* __restrict__ bbv) {
    __shared__ float xs[64][36];
    __shared__ float ws[32][33];   // transposed: ws[k][col]
    const int tid  = threadIdx.x;
    const int row0 = blockIdx.x * 64;
    const int c    = tid & 31;     // 0..31 : 0..15 alpha heads, 16..31 beta heads
    const int rg   = tid >> 5;     // 0..7

    float acc[8];
    #pragma unroll
    for (int i = 0; i < 8; i++) acc[i] = 0.f;

    for (int k0 = 0; k0 < DD; k0 += 32) {
        __syncthreads();
        #pragma unroll
        for (int i = 0; i < 2; i++) {
            const int f = tid + i*256;            // 0..511
            const int r = f >> 3, c4 = (f & 7)*4;
            float4 val = *(const float4*)(X + (size_t)(row0 + r)*DD + k0 + c4);
            *(float4*)&xs[r][c4] = val;
        }
        #pragma unroll
        for (int i = 0; i < 4; i++) {
            const int f = tid + i*256;            // 0..1023
            const int o = f >> 5, kkk = f & 31;
            const float* wr = (o < 16) ? (Wa + (size_t)o*DD) : (Wb + (size_t)(o - 16)*DD);
            ws[kkk][o] = wr[k0 + kkk];
        }
        __syncthreads();
        #pragma unroll 4
        for (int kkk = 0; kkk < 32; ++kkk) {
            const float w = ws[kkk][c];
            #pragma unroll
            for (int i = 0; i < 8; i++) acc[i] = fmaf(xs[rg*8 + i][kkk], w, acc[i]);
        }
    }

    #pragma unroll
    for (int i = 0; i < 8; i++) {
        const int bt = row0 + rg*8 + i;
        if (c < 16) {
            const float z = acc[i] + ba[c];
            g_alpha[(size_t)bt*HHN + c] = 1.f / (1.f + expf(-z));
        } else {
            const int h = c - 16;
            const float z = acc[i] + bbv[h];
            const float sp = fmaxf(z, 0.f) + log1pf(expf(-fabsf(z)));
            g_beta[(size_t)bt*HHN + h] = sp * 0.088388347648318447f;  // 128^-0.5
        }
    }
}

// ---------------------------------------------------------------------------
// l2norm of q,k rows (each row = 128 floats). One warp per row (both tensors).
// ---------------------------------------------------------------------------
__global__ __launch_bounds__(256)
void gdn_l2norm_kernel() {
    const int gw   = (blockIdx.x * 256 + threadIdx.x) >> 5;  // 0..65535
    const int lane = threadIdx.x & 31;
    {
        float4* p = reinterpret_cast<float4*>(g_q) + (size_t)gw*32 + lane;
        float4 v = *p;
        float s = v.x*v.x + v.y*v.y + v.z*v.z + v.w*v.w;
        #pragma unroll
        for (int o = 16; o; o >>= 1) s += __shfl_xor_sync(0xffffffffu, s, o);
        const float inv = 1.0f / fmaxf(sqrtf(s), 1e-12f);
        v.x *= inv; v.y *= inv; v.z *= inv; v.w *= inv;
        *p = v;
    }
    {
        float4* p = reinterpret_cast<float4*>(g_k) + (size_t)gw*32 + lane;
        float4 v = *p;
        float s = v.x*v.x + v.y*v.y + v.z*v.z + v.w*v.w;
        #pragma unroll
        for (int o = 16; o; o >>= 1) s += __shfl_xor_sync(0xffffffffu, s, o);
        const float inv = 1.0f / fmaxf(sqrtf(s), 1e-12f);
        v.x *= inv; v.y *= inv; v.z *= inv; v.w *= inv;
        *p = v;
    }
}

// ---------------------------------------------------------------------------
// Gated delta-rule scan. V-rows are independent: grid (4 vblk, 16 h, 2 b),
// 128 threads/CTA. Warp = 8 v-rows x 4 k-groups; thread owns S[1 v][32 k] in
// registers. Only cross-thread comm: shfl_xor(8/16) reductions. No smem/sync.
// k/q/v/alpha/beta for t+1 register-prefetched each step.
// ---------------------------------------------------------------------------
__global__ __launch_bounds__(128, 1)
void gdn_scan_kernel(float* __restrict__ out) {
    const int b    = blockIdx.z;
    const int h    = blockIdx.y;
    const int w    = threadIdx.x >> 5;
    const int lane = threadIdx.x & 31;
    const int vi   = lane & 7;
    const int kg   = lane >> 3;
    const int vrow = blockIdx.x*32 + w*8 + vi;
    const int koff = kg * 32;

    const float* qb  = g_q     + (size_t)b*TT*HK + h*KKD + koff;
    const float* kb  = g_k     + (size_t)b*TT*HK + h*KKD + koff;
    const float* vb  = g_v     + (size_t)b*TT*HK + h*VVD + vrow;
    const float* ab  = g_alpha + (size_t)b*TT*HHN + h;
    const float* btb = g_beta  + (size_t)b*TT*HHN + h;
    float*       ob  = out     + (size_t)b*TT*HK + h*VVD + vrow;

    float S[32];
    #pragma unroll
    for (int i = 0; i < 32; i++) S[i] = 0.f;

    float4 kc[8], qc[8], kn[8], qn[8];
    float vc, ac, bc, vn, an, bn;

    {
        const float4* k4 = (const float4*)kb;
        const float4* q4 = (const float4*)qb;
        #pragma unroll
        for (int i = 0; i < 8; i++) { kc[i] = k4[i]; qc[i] = q4[i]; }
        vc = vb[0]; ac = ab[0]; bc = btb[0];
    }

    auto step = [&](int t,
                    float4 (&KC)[8], float4 (&QC)[8], float& VC, float& AC, float& BC,
                    float4 (&KN)[8], float4 (&QN)[8], float& VN, float& AN, float& BN) {
        const int tn = t + 1;
        if (tn < TT) {
            const float4* k4 = (const float4*)(kb + (size_t)tn*HK);
            const float4* q4 = (const float4*)(qb + (size_t)tn*HK);
            #pragma unroll
            for (int i = 0; i < 8; i++) { KN[i] = k4[i]; QN[i] = q4[i]; }
            VN = vb[(size_t)tn*HK];
            AN = ab[(size_t)tn*HHN];
            BN = btb[(size_t)tn*HHN];
        }
        // pred (partial over this thread's 32 k)
        float p0 = 0.f, p1 = 0.f, p2 = 0.f, p3 = 0.f;
        #pragma unroll
        for (int i = 0; i < 8; i++) {
            p0 = fmaf(S[4*i+0], KC[i].x, p0);
            p1 = fmaf(S[4*i+1], KC[i].y, p1);
            p2 = fmaf(S[4*i+2], KC[i].z, p2);
            p3 = fmaf(S[4*i+3], KC[i].w, p3);
        }
        float pred = (p0 + p1) + (p2 + p3);
        pred += __shfl_xor_sync(0xffffffffu, pred, 8);
        pred += __shfl_xor_sync(0xffffffffu, pred, 16);
        const float u = BC * (VC - AC*pred);
        // update + output
        float o0 = 0.f, o1 = 0.f, o2 = 0.f, o3 = 0.f;
        #pragma unroll
        for (int i = 0; i < 8; i++) {
            float s;
            s = fmaf(u, KC[i].x, AC*S[4*i+0]); S[4*i+0] = s; o0 = fmaf(s, QC[i].x, o0);
            s = fmaf(u, KC[i].y, AC*S[4*i+1]); S[4*i+1] = s; o1 = fmaf(s, QC[i].y, o1);
            s = fmaf(u, KC[i].z, AC*S[4*i+2]); S[4*i+2] = s; o2 = fmaf(s, QC[i].z, o2);
            s = fmaf(u, KC[i].w, AC*S[4*i+3]); S[4*i+3] = s; o3 = fmaf(s, QC[i].w, o3);
        }
        float o = (o0 + o1) + (o2 + o3);
        o += __shfl_xor_sync(0xffffffffu, o, 8);
        o += __shfl_xor_sync(0xffffffffu, o, 16);
        if (kg == 0) ob[(size_t)t*HK] = o;
    };

    for (int t = 0; t < TT; t += 2) {
        step(t,     kc, qc, vc, ac, bc, kn, qn, vn, an, bn);
        step(t + 1, kn, qn, vn, an, bn, kc, qc, vc, ac, bc);
    }
}

// ---------------------------------------------------------------------------
extern "C" void kernel_launch(void* const* d_in, const int* in_sizes, int n_in,
                              void* d_out, int out_size) {
    const float* x   = (const float*)d_in[0];
    const float* Wq  = (const float*)d_in[1];
    const float* Wk  = (const float*)d_in[2];
    const float* Wv  = (const float*)d_in[3];
    const float* Wa  = (const float*)d_in[4];
    const float* ba  = (const float*)d_in[5];
    const float* Wb  = (const float*)d_in[6];
    const float* bbv = (const float*)d_in[7];
    float* out = (float*)d_out;

    dim3 ggrid(HK/128, BT/128, 3);           // (16, 32, 3)
    gdn_proj_gemm<<<ggrid, 256>>>(x, Wq, Wk, Wv);
    gdn_ab_kernel<<<BT/64, 256>>>(x, Wa, ba, Wb, bbv);
    gdn_l2norm_kernel<<<(BT*HHN)/8, 256>>>();
    gdn_scan_kernel<<<dim3(4, HHN, BB), 128>>>(out);
}

// round 6
// speedup vs baseline: 1.1414x; 1.1414x over previous
#include <cuda_runtime.h>
#include <math.h>
#include <stdint.h>

typedef unsigned long long ull;

// Problem dims (fixed)
#define BB 2
#define TT 2048
#define DD 2048
#define HHN 16
#define KKD 128
#define VVD 128
#define BT  (BB*TT)     // 4096
#define HK  (HHN*KKD)   // 2048

// Scratch (device globals: no allocation allowed)
__device__ float g_q[BT*HK];
__device__ float g_k[BT*HK];
__device__ float g_v[BT*HK];
__device__ float g_alpha[BT*HHN];
__device__ float g_beta[BT*HHN];
__device__ float g_xc[BT*DD];      // tf32-rounded X
__device__ float g_wqc[HK*DD];     // tf32-rounded weights
__device__ float g_wkc[HK*DD];
__device__ float g_wvc[HK*DD];

// ---------------------------------------------------------------------------
// helpers
// ---------------------------------------------------------------------------
__device__ __forceinline__ float to_tf32(float x) {
    asm("cvt.rna.tf32.f32 %0, %0;" : "+f"(x));
    return x;
}
__device__ __forceinline__ uint32_t smem_u32(const void* p) {
    uint32_t a;
    asm("{ .reg .u64 t; cvta.to.shared.u64 t, %1; cvt.u32.u64 %0, t; }" : "=r"(a) : "l"(p));
    return a;
}
__device__ __forceinline__ void cp16(uint32_t dst, const void* src) {
    asm volatile("cp.async.cg.shared.global [%0], [%1], 16;" :: "r"(dst), "l"(src));
}
#define CP_COMMIT() asm volatile("cp.async.commit_group;" ::: "memory")

__device__ __forceinline__ void mma_tf32(float* d, const uint32_t* a, const uint32_t* b) {
    asm volatile("mma.sync.aligned.m16n8k8.row.col.f32.tf32.tf32.f32 "
        "{%0,%1,%2,%3}, {%4,%5,%6,%7}, {%8,%9}, {%0,%1,%2,%3};"
        : "+f"(d[0]), "+f"(d[1]), "+f"(d[2]), "+f"(d[3])
        : "r"(a[0]), "r"(a[1]), "r"(a[2]), "r"(a[3]), "r"(b[0]), "r"(b[1]));
}

// ---------------------------------------------------------------------------
// tf32-round conversion (pre-pass so cp.async can copy raw bits)
// ---------------------------------------------------------------------------
__global__ __launch_bounds__(256)
void gdn_conv_kernel(const float* __restrict__ src, float* __restrict__ dst, int n4) {
    int i = blockIdx.x * 256 + threadIdx.x;
    const int stride = gridDim.x * 256;
    const float4* s = (const float4*)src;
    float4* d = (float4*)dst;
    for (; i < n4; i += stride) {
        float4 v = s[i];
        v.x = to_tf32(v.x); v.y = to_tf32(v.y);
        v.z = to_tf32(v.z); v.w = to_tf32(v.w);
        d[i] = v;
    }
}

// ---------------------------------------------------------------------------
// Projection GEMM v2: C[4096,2048] = X @ W^T, tf32 mma.sync m16n8k8.
// BM=BN=128, BK=16, 3-stage cp.async ring, 256 thr, 8 warps, warp tile 32x64.
// Smem rows padded to 20 floats: cp.async 16B chunks land 16B-aligned
// (20*4=80B row stride) and fragment LDS is bank-conflict-free.
// ---------------------------------------------------------------------------
#define SSTR 20
#define STG_FLOATS (128*SSTR)                 // one A or B stage
#define STG_BYTES  (STG_FLOATS*4)             // 10240
#define GEMM_SMEM  (3*2*STG_BYTES)            // 61440

__global__ __launch_bounds__(256, 2)
void gdn_proj_gemm() {
    extern __shared__ __align__(16) float smem[];
    const uint32_t sb = smem_u32(smem);

    const float* X = g_xc;
    const float* W; float* C;
    if (blockIdx.z == 0)      { W = g_wqc; C = g_q; }
    else if (blockIdx.z == 1) { W = g_wkc; C = g_k; }
    else                      { W = g_wvc; C = g_v; }

    const int tid  = threadIdx.x;
    const int lane = tid & 31;
    const int wid  = tid >> 5;
    const int wm   = wid >> 1;      // 0..3
    const int wn   = wid & 1;       // 0..1
    const int g    = lane >> 2;     // 0..7
    const int tig  = lane & 3;      // 0..3

    const int rowA = blockIdx.y * 128;
    const int rowB = blockIdx.x * 128;

    // cp.async mapping: 1024 16B-chunks per (A+B) stage, 4 per thread
    const int lrow = tid >> 2;              // 0..63  (two rows per thread: lrow, lrow+64)
    const int lcid = (tid & 3) * 16;        // byte col within 64B row: 0,16,32,48
    const int lcf  = (tid & 3) * 4;         // float col: 0,4,8,12

    auto load_stage = [&](int kt) {
        const int s = kt % 3;
        const uint32_t abase = sb + s * 2 * STG_BYTES;
        const uint32_t bbase = abase + STG_BYTES;
        const int k0 = kt * 16;
        cp16(abase + (uint32_t)lrow * 80 + lcid,        X + (size_t)(rowA + lrow) * DD + k0 + lcf);
        cp16(abase + (uint32_t)(lrow + 64) * 80 + lcid, X + (size_t)(rowA + lrow + 64) * DD + k0 + lcf);
        cp16(bbase + (uint32_t)lrow * 80 + lcid,        W + (size_t)(rowB + lrow) * DD + k0 + lcf);
        cp16(bbase + (uint32_t)(lrow + 64) * 80 + lcid, W + (size_t)(rowB + lrow + 64) * DD + k0 + lcf);
        CP_COMMIT();
    };

    float acc[2][8][4];
    #pragma unroll
    for (int i = 0; i < 2; i++)
        #pragma unroll
        for (int j = 0; j < 8; j++)
            #pragma unroll
            for (int l = 0; l < 4; l++) acc[i][j][l] = 0.f;

    load_stage(0);
    load_stage(1);

    const int KT = DD / 16;   // 128
    for (int kt = 0; kt < KT; ++kt) {
        asm volatile("cp.async.wait_group 1;" ::: "memory");
        __syncthreads();

        // keep the ring full (empty commit keeps wait_group accounting uniform)
        if (kt + 2 < KT) load_stage(kt + 2); else CP_COMMIT();

        const int s = kt % 3;
        const float* As = smem + s * 2 * STG_FLOATS;
        const float* Bs = As + STG_FLOATS;

        #pragma unroll
        for (int kk = 0; kk < 16; kk += 8) {
            uint32_t afr[2][4], bfr[8][2];
            #pragma unroll
            for (int mt = 0; mt < 2; mt++) {
                const int rb = wm*32 + mt*16;
                afr[mt][0] = __float_as_uint(As[(rb + g    )*SSTR + kk + tig    ]);
                afr[mt][1] = __float_as_uint(As[(rb + g + 8)*SSTR + kk + tig    ]);
                afr[mt][2] = __float_as_uint(As[(rb + g    )*SSTR + kk + tig + 4]);
                afr[mt][3] = __float_as_uint(As[(rb + g + 8)*SSTR + kk + tig + 4]);
            }
            #pragma unroll
            for (int nt = 0; nt < 8; nt++) {
                const int cb = wn*64 + nt*8;
                bfr[nt][0] = __float_as_uint(Bs[(cb + g)*SSTR + kk + tig    ]);
                bfr[nt][1] = __float_as_uint(Bs[(cb + g)*SSTR + kk + tig + 4]);
            }
            #pragma unroll
            for (int mt = 0; mt < 2; mt++)
                #pragma unroll
                for (int nt = 0; nt < 8; nt++)
                    mma_tf32(acc[mt][nt], afr[mt], bfr[nt]);
        }
        __syncthreads();
    }

    // epilogue
    #pragma unroll
    for (int mt = 0; mt < 2; mt++) {
        #pragma unroll
        for (int nt = 0; nt < 8; nt++) {
            const int r  = rowA + wm*32 + mt*16 + g;
            const int cc = rowB + wn*64 + nt*8 + tig*2;
            *(float2*)(C + (size_t)r*HK + cc)       = make_float2(acc[mt][nt][0], acc[mt][nt][1]);
            *(float2*)(C + (size_t)(r + 8)*HK + cc) = make_float2(acc[mt][nt][2], acc[mt][nt][3]);
        }
    }
}

// ---------------------------------------------------------------------------
// alpha/beta: [4096,32] = X @ [Wa;Wb]^T, then sigmoid / softplus*K^-0.5.
// ---------------------------------------------------------------------------
__global__ __launch_bounds__(256)
void gdn_ab_kernel(const float* __restrict__ X,
                   const float* __restrict__ Wa, const float* __restrict__ ba,
                   const float* __restrict__ Wb, const float* __restrict__ bbv) {
    __shared__ float xs[64][36];
    __shared__ float ws[32][33];
    const int tid  = threadIdx.x;
    const int row0 = blockIdx.x * 64;
    const int c    = tid & 31;
    const int rg   = tid >> 5;

    float acc[8];
    #pragma unroll
    for (int i = 0; i < 8; i++) acc[i] = 0.f;

    for (int k0 = 0; k0 < DD; k0 += 32) {
        __syncthreads();
        #pragma unroll
        for (int i = 0; i < 2; i++) {
            const int f = tid + i*256;
            const int r = f >> 3, c4 = (f & 7)*4;
            float4 val = *(const float4*)(X + (size_t)(row0 + r)*DD + k0 + c4);
            *(float4*)&xs[r][c4] = val;
        }
        #pragma unroll
        for (int i = 0; i < 4; i++) {
            const int f = tid + i*256;
            const int o = f >> 5, kkk = f & 31;
            const float* wr = (o < 16) ? (Wa + (size_t)o*DD) : (Wb + (size_t)(o - 16)*DD);
            ws[kkk][o] = wr[k0 + kkk];
        }
        __syncthreads();
        #pragma unroll 4
        for (int kkk = 0; kkk < 32; ++kkk) {
            const float w = ws[kkk][c];
            #pragma unroll
            for (int i = 0; i < 8; i++) acc[i] = fmaf(xs[rg*8 + i][kkk], w, acc[i]);
        }
    }

    #pragma unroll
    for (int i = 0; i < 8; i++) {
        const int bt = row0 + rg*8 + i;
        if (c < 16) {
            const float z = acc[i] + ba[c];
            g_alpha[(size_t)bt*HHN + c] = 1.f / (1.f + expf(-z));
        } else {
            const int h = c - 16;
            const float z = acc[i] + bbv[h];
            const float sp = fmaxf(z, 0.f) + log1pf(expf(-fabsf(z)));
            g_beta[(size_t)bt*HHN + h] = sp * 0.088388347648318447f;
        }
    }
}

// ---------------------------------------------------------------------------
// l2norm of q,k rows (each row = 128 floats). One warp per row.
// ---------------------------------------------------------------------------
__global__ __launch_bounds__(256)
void gdn_l2norm_kernel() {
    const int gw   = (blockIdx.x * 256 + threadIdx.x) >> 5;
    const int lane = threadIdx.x & 31;
    {
        float4* p = reinterpret_cast<float4*>(g_q) + (size_t)gw*32 + lane;
        float4 v = *p;
        float s = v.x*v.x + v.y*v.y + v.z*v.z + v.w*v.w;
        #pragma unroll
        for (int o = 16; o; o >>= 1) s += __shfl_xor_sync(0xffffffffu, s, o);
        const float inv = 1.0f / fmaxf(sqrtf(s), 1e-12f);
        v.x *= inv; v.y *= inv; v.z *= inv; v.w *= inv;
        *p = v;
    }
    {
        float4* p = reinterpret_cast<float4*>(g_k) + (size_t)gw*32 + lane;
        float4 v = *p;
        float s = v.x*v.x + v.y*v.y + v.z*v.z + v.w*v.w;
        #pragma unroll
        for (int o = 16; o; o >>= 1) s += __shfl_xor_sync(0xffffffffu, s, o);
        const float inv = 1.0f / fmaxf(sqrtf(s), 1e-12f);
        v.x *= inv; v.y *= inv; v.z *= inv; v.w *= inv;
        *p = v;
    }
}

// ---------------------------------------------------------------------------
// Gated delta-rule scan v3: thread = 1 v-row x 8 k (f32x2 packed),
// warp = 2 v-rows x 16 k-groups, CTA = 128 thr = 8 v-rows.
// grid (16 vblk, 16 h, 2 b) = 512 CTAs x 4 warps -> ~3.5 warps/SMSP.
// ---------------------------------------------------------------------------
__device__ __forceinline__ ull f2fma(ull a, ull b, ull c) {
    ull d; asm("fma.rn.f32x2 %0, %1, %2, %3;" : "=l"(d) : "l"(a), "l"(b), "l"(c)); return d;
}
__device__ __forceinline__ ull f2mul(ull a, ull b) {
    ull d; asm("mul.rn.f32x2 %0, %1, %2;" : "=l"(d) : "l"(a), "l"(b)); return d;
}
__device__ __forceinline__ ull f2add(ull a, ull b) {
    ull d; asm("add.rn.f32x2 %0, %1, %2;" : "=l"(d) : "l"(a), "l"(b)); return d;
}
__device__ __forceinline__ ull f2pack(float lo, float hi) {
    ull d; asm("mov.b64 %0, {%1, %2};" : "=l"(d) : "f"(lo), "f"(hi)); return d;
}
__device__ __forceinline__ float f2hsum(ull a) {
    float lo, hi; asm("mov.b64 {%0, %1}, %2;" : "=f"(lo), "=f"(hi) : "l"(a)); return lo + hi;
}

__global__ __launch_bounds__(128, 4)
void gdn_scan_kernel(float* __restrict__ out) {
    const int b    = blockIdx.z;
    const int h    = blockIdx.y;
    const int w    = threadIdx.x >> 5;
    const int lane = threadIdx.x & 31;
    const int vi   = lane >> 4;        // 0..1
    const int kg   = lane & 15;        // 0..15 -> 8 k each
    const int vrow = blockIdx.x*8 + w*2 + vi;
    const int koff = kg * 8;

    const float* qb  = g_q     + (size_t)b*TT*HK + h*KKD + koff;
    const float* kb  = g_k     + (size_t)b*TT*HK + h*KKD + koff;
    const float* vb  = g_v     + (size_t)b*TT*HK + h*VVD + vrow;
    const float* ab  = g_alpha + (size_t)b*TT*HHN + h;
    const float* btb = g_beta  + (size_t)b*TT*HHN + h;
    float*       ob  = out     + (size_t)b*TT*HK + h*VVD + vrow;

    ull S0 = 0, S1 = 0, S2 = 0, S3 = 0;
    ull kc0, kc1, kc2, kc3, qc0, qc1, qc2, qc3;
    ull kn0, kn1, kn2, kn3, qn0, qn1, qn2, qn3;
    float vc, ac, bc, vn, an, bn;

    {
        const ulonglong2* kp = (const ulonglong2*)kb;
        const ulonglong2* qp = (const ulonglong2*)qb;
        ulonglong2 a0 = kp[0], a1 = kp[1], b0 = qp[0], b1 = qp[1];
        kc0 = a0.x; kc1 = a0.y; kc2 = a1.x; kc3 = a1.y;
        qc0 = b0.x; qc1 = b0.y; qc2 = b1.x; qc3 = b1.y;
        vc = vb[0]; ac = ab[0]; bc = btb[0];
    }

    auto step = [&](int t,
                    ull& KC0, ull& KC1, ull& KC2, ull& KC3,
                    ull& QC0, ull& QC1, ull& QC2, ull& QC3,
                    float& VC, float& AC, float& BC,
                    ull& KN0, ull& KN1, ull& KN2, ull& KN3,
                    ull& QN0, ull& QN1, ull& QN2, ull& QN3,
                    float& VN, float& AN, float& BN) {
        const int tn = t + 1;
        if (tn < TT) {
            const ulonglong2* kp = (const ulonglong2*)(kb + (size_t)tn*HK);
            const ulonglong2* qp = (const ulonglong2*)(qb + (size_t)tn*HK);
            ulonglong2 a0 = kp[0], a1 = kp[1], b0 = qp[0], b1 = qp[1];
            KN0 = a0.x; KN1 = a0.y; KN2 = a1.x; KN3 = a1.y;
            QN0 = b0.x; QN1 = b0.y; QN2 = b1.x; QN3 = b1.y;
            VN = vb[(size_t)tn*HK];
            AN = ab[(size_t)tn*HHN];
            BN = btb[(size_t)tn*HHN];
        }
        // pred partial over this thread's 8 k
        ull p01 = f2fma(S1, KC1, f2mul(S0, KC0));
        ull p23 = f2fma(S3, KC3, f2mul(S2, KC2));
        float pred = f2hsum(f2add(p01, p23));
        #pragma unroll
        for (int o = 1; o <= 8; o <<= 1) pred += __shfl_xor_sync(0xffffffffu, pred, o);

        const float u = BC * (VC - AC * pred);
        const ull a2 = f2pack(AC, AC);
        const ull u2 = f2pack(u, u);

        S0 = f2fma(u2, KC0, f2mul(a2, S0));
        S1 = f2fma(u2, KC1, f2mul(a2, S1));
        S2 = f2fma(u2, KC2, f2mul(a2, S2));
        S3 = f2fma(u2, KC3, f2mul(a2, S3));

        ull o01 = f2fma(S1, QC1, f2mul(S0, QC0));
        ull o23 = f2fma(S3, QC3, f2mul(S2, QC2));
        float o = f2hsum(f2add(o01, o23));
        #pragma unroll
        for (int of = 1; of <= 8; of <<= 1) o += __shfl_xor_sync(0xffffffffu, o, of);
        if (kg == 0) ob[(size_t)t*HK] = o;
    };

    for (int t = 0; t < TT; t += 2) {
        step(t,     kc0,kc1,kc2,kc3, qc0,qc1,qc2,qc3, vc,ac,bc,
                    kn0,kn1,kn2,kn3, qn0,qn1,qn2,qn3, vn,an,bn);
        step(t + 1, kn0,kn1,kn2,kn3, qn0,qn1,qn2,qn3, vn,an,bn,
                    kc0,kc1,kc2,kc3, qc0,qc1,qc2,qc3, vc,ac,bc);
    }
}

// ---------------------------------------------------------------------------
extern "C" void kernel_launch(void* const* d_in, const int* in_sizes, int n_in,
                              void* d_out, int out_size) {
    const float* x   = (const float*)d_in[0];
    const float* Wq  = (const float*)d_in[1];
    const float* Wk  = (const float*)d_in[2];
    const float* Wv  = (const float*)d_in[3];
    const float* Wa  = (const float*)d_in[4];
    const float* ba  = (const float*)d_in[5];
    const float* Wb  = (const float*)d_in[6];
    const float* bbv = (const float*)d_in[7];
    float* out = (float*)d_out;

    float* xc;  cudaGetSymbolAddress((void**)&xc,  g_xc);
    float* wqc; cudaGetSymbolAddress((void**)&wqc, g_wqc);
    float* wkc; cudaGetSymbolAddress((void**)&wkc, g_wkc);
    float* wvc; cudaGetSymbolAddress((void**)&wvc, g_wvc);

    cudaFuncSetAttribute(gdn_proj_gemm, cudaFuncAttributeMaxDynamicSharedMemorySize, GEMM_SMEM);

    gdn_conv_kernel<<<1024, 256>>>(x,  xc,  BT*DD/4);
    gdn_conv_kernel<<<1024, 256>>>(Wq, wqc, HK*DD/4);
    gdn_conv_kernel<<<1024, 256>>>(Wk, wkc, HK*DD/4);
    gdn_conv_kernel<<<1024, 256>>>(Wv, wvc, HK*DD/4);

    gdn_proj_gemm<<<dim3(HK/128, BT/128, 3), 256, GEMM_SMEM>>>();  // (16, 32, 3)
    gdn_ab_kernel<<<BT/64, 256>>>(x, Wa, ba, Wb, bbv);
    gdn_l2norm_kernel<<<(BT*HHN)/8, 256>>>();
    gdn_scan_kernel<<<dim3(16, HHN, BB), 128>>>(out);
}

// round 9
// speedup vs baseline: 1.3511x; 1.1837x over previous
#include <cuda_runtime.h>
#include <cuda_fp16.h>
#include <math.h>
#include <stdint.h>

typedef unsigned long long ull;

// Problem dims (fixed)
#define BB 2
#define TT 2048
#define DD 2048
#define HHN 16
#define KKD 128
#define VVD 128
#define BT  (BB*TT)     // 4096
#define HK  (HHN*KKD)   // 2048

// Scratch (device globals: no allocation allowed)
__device__ float g_q[BT*HK];
__device__ float g_k[BT*HK];
__device__ float g_v[BT*HK];
__device__ float g_alpha[BT*HHN];
__device__ float g_beta[BT*HHN];
__device__ float g_kq[BT*HHN];
__device__ __half g_xh[BT*DD];     // fp16 X
__device__ __half g_wqh[HK*DD];    // fp16 weights
__device__ __half g_wkh[HK*DD];
__device__ __half g_wvh[HK*DD];

// ---------------------------------------------------------------------------
// helpers
// ---------------------------------------------------------------------------
__device__ __forceinline__ uint32_t smem_u32(const void* p) {
    uint32_t a;
    asm("{ .reg .u64 t; cvta.to.shared.u64 t, %1; cvt.u32.u64 %0, t; }" : "=r"(a) : "l"(p));
    return a;
}
__device__ __forceinline__ void cp16(uint32_t dst, const void* src) {
    asm volatile("cp.async.cg.shared.global [%0], [%1], 16;" :: "r"(dst), "l"(src));
}
#define CP_COMMIT() asm volatile("cp.async.commit_group;" ::: "memory")

__device__ __forceinline__ uint32_t h2_bits(__half2 h) {
    union { __half2 h; uint32_t u; } cv; cv.h = h; return cv.u;
}

__device__ __forceinline__ void mma_f16(float* d, const uint32_t* a, const uint32_t* b) {
    asm volatile("mma.sync.aligned.m16n8k16.row.col.f32.f16.f16.f32 "
        "{%0,%1,%2,%3}, {%4,%5,%6,%7}, {%8,%9}, {%0,%1,%2,%3};"
        : "+f"(d[0]), "+f"(d[1]), "+f"(d[2]), "+f"(d[3])
        : "r"(a[0]), "r"(a[1]), "r"(a[2]), "r"(a[3]), "r"(b[0]), "r"(b[1]));
}

// ---------------------------------------------------------------------------
// f32 -> fp16 conversion pre-pass (8 floats per thread-iter, 16B stores)
// ---------------------------------------------------------------------------
__global__ __launch_bounds__(256)
void gdn_convh_kernel(const float* __restrict__ src, uint4* __restrict__ dst, int n8) {
    int i = blockIdx.x * 256 + threadIdx.x;
    const int stride = gridDim.x * 256;
    const float4* s = (const float4*)src;
    for (; i < n8; i += stride) {
        float4 a = s[2*i], b = s[2*i+1];
        uint4 o;
        o.x = h2_bits(__floats2half2_rn(a.x, a.y));
        o.y = h2_bits(__floats2half2_rn(a.z, a.w));
        o.z = h2_bits(__floats2half2_rn(b.x, b.y));
        o.w = h2_bits(__floats2half2_rn(b.z, b.w));
        dst[i] = o;
    }
}

// ---------------------------------------------------------------------------
// Projection GEMM v3 (fp16 m16n8k16): C[4096,2048] = X @ W^T.
// BM=BN=128, BK=32 halves, 3-stage cp.async ring, 256 thr, 8 warps (4x2),
// warp tile 32x64. Smem rows = 40 halves (80B): cp.async 16B chunks aligned,
// fragment LDS.32 conflict-free.
// ---------------------------------------------------------------------------
#define RS   40                              // halves per smem row
#define STG_H (128*RS)                       // halves per tensor per stage: 5120
#define STG_BYTES (STG_H*2)                  // 10240
#define GEMM_SMEM (3*2*STG_BYTES)            // 61440

__global__ __launch_bounds__(256, 2)
void gdn_proj_gemm() {
    extern __shared__ __align__(16) __half hsm[];

    const __half* X = g_xh;
    const __half* W; float* C;
    if (blockIdx.z == 0)      { W = g_wqh; C = g_q; }
    else if (blockIdx.z == 1) { W = g_wkh; C = g_k; }
    else                      { W = g_wvh; C = g_v; }

    const int tid  = threadIdx.x;
    const int lane = tid & 31;
    const int wid  = tid >> 5;
    const int wm   = wid >> 1;      // 0..3
    const int wn   = wid & 1;       // 0..1
    const int g    = lane >> 2;     // 0..7
    const int tig  = lane & 3;      // 0..3

    const int rowA = blockIdx.y * 128;
    const int rowB = blockIdx.x * 128;

    // cp.async: per stage A 128 rows x 4 chunks + B same = 1024 chunks, 4/thread
    const int lrow = tid >> 2;              // 0..63 (rows lrow, lrow+64)
    const int lcb  = (tid & 3) * 16;        // dst byte col: 0,16,32,48
    const int lch  = (tid & 3) * 8;         // src half col: 0,8,16,24

    const uint32_t sb = smem_u32(hsm);

    auto load_stage = [&](int kt) {
        const int s = kt % 3;
        const uint32_t abase = sb + s * 2 * STG_BYTES;
        const uint32_t bbase = abase + STG_BYTES;
        const int k0 = kt * 32;
        cp16(abase + (uint32_t)lrow * 80 + lcb,        X + (size_t)(rowA + lrow) * DD + k0 + lch);
        cp16(abase + (uint32_t)(lrow + 64) * 80 + lcb, X + (size_t)(rowA + lrow + 64) * DD + k0 + lch);
        cp16(bbase + (uint32_t)lrow * 80 + lcb,        W + (size_t)(rowB + lrow) * DD + k0 + lch);
        cp16(bbase + (uint32_t)(lrow + 64) * 80 + lcb, W + (size_t)(rowB + lrow + 64) * DD + k0 + lch);
        CP_COMMIT();
    };

    float acc[2][8][4];
    #pragma unroll
    for (int i = 0; i < 2; i++)
        #pragma unroll
        for (int j = 0; j < 8; j++)
            #pragma unroll
            for (int l = 0; l < 4; l++) acc[i][j][l] = 0.f;

    load_stage(0);
    load_stage(1);

    const int KT = DD / 32;   // 64
    for (int kt = 0; kt < KT; ++kt) {
        asm volatile("cp.async.wait_group 1;" ::: "memory");
        __syncthreads();

        if (kt + 2 < KT) load_stage(kt + 2); else CP_COMMIT();

        const int s = kt % 3;
        const uint32_t* As32 = (const uint32_t*)(hsm + (size_t)s * 2 * STG_H);
        const uint32_t* Bs32 = As32 + STG_H / 2;

        #pragma unroll
        for (int kk2 = 0; kk2 < 16; kk2 += 8) {   // two k16 steps per BK=32
            uint32_t afr[2][4], bfr[8][2];
            #pragma unroll
            for (int mt = 0; mt < 2; mt++) {
                const int rb = wm*32 + mt*16;
                afr[mt][0] = As32[(rb + g    )*20 + kk2 + tig    ];
                afr[mt][1] = As32[(rb + g + 8)*20 + kk2 + tig    ];
                afr[mt][2] = As32[(rb + g    )*20 + kk2 + tig + 4];
                afr[mt][3] = As32[(rb + g + 8)*20 + kk2 + tig + 4];
            }
            #pragma unroll
            for (int nt = 0; nt < 8; nt++) {
                const int cb = wn*64 + nt*8;
                bfr[nt][0] = Bs32[(cb + g)*20 + kk2 + tig    ];
                bfr[nt][1] = Bs32[(cb + g)*20 + kk2 + tig + 4];
            }
            #pragma unroll
            for (int mt = 0; mt < 2; mt++)
                #pragma unroll
                for (int nt = 0; nt < 8; nt++)
                    mma_f16(acc[mt][nt], afr[mt], bfr[nt]);
        }
        __syncthreads();
    }

    // epilogue (m16n8 f32 layout)
    #pragma unroll
    for (int mt = 0; mt < 2; mt++) {
        #pragma unroll
        for (int nt = 0; nt < 8; nt++) {
            const int r  = rowA + wm*32 + mt*16 + g;
            const int cc = rowB + wn*64 + nt*8 + tig*2;
            *(float2*)(C + (size_t)r*HK + cc)       = make_float2(acc[mt][nt][0], acc[mt][nt][1]);
            *(float2*)(C + (size_t)(r + 8)*HK + cc) = make_float2(acc[mt][nt][2], acc[mt][nt][3]);
        }
    }
}

// ---------------------------------------------------------------------------
// alpha/beta: [4096,32] = X @ [Wa;Wb]^T, then sigmoid / softplus*K^-0.5.
// ---------------------------------------------------------------------------
__global__ __launch_bounds__(256)
void gdn_ab_kernel(const float* __restrict__ X,
                   const float* __restrict__ Wa, const float* __restrict__ ba,
                   const float* __restrict__ Wb, const float* __restrict__ bbv) {
    __shared__ float xs[64][36];
    __shared__ float ws[32][33];
    const int tid  = threadIdx.x;
    const int row0 = blockIdx.x * 64;
    const int c    = tid & 31;
    const int rg   = tid >> 5;

    float acc[8];
    #pragma unroll
    for (int i = 0; i < 8; i++) acc[i] = 0.f;

    for (int k0 = 0; k0 < DD; k0 += 32) {
        __syncthreads();
        #pragma unroll
        for (int i = 0; i < 2; i++) {
            const int f = tid + i*256;
            const int r = f >> 3, c4 = (f & 7)*4;
            float4 val = *(const float4*)(X + (size_t)(row0 + r)*DD + k0 + c4);
            *(float4*)&xs[r][c4] = val;
        }
        #pragma unroll
        for (int i = 0; i < 4; i++) {
            const int f = tid + i*256;
            const int o = f >> 5, kkk = f & 31;
            const float* wr = (o < 16) ? (Wa + (size_t)o*DD) : (Wb + (size_t)(o - 16)*DD);
            ws[kkk][o] = wr[k0 + kkk];
        }
        __syncthreads();
        #pragma unroll 4
        for (int kkk = 0; kkk < 32; ++kkk) {
            const float w = ws[kkk][c];
            #pragma unroll
            for (int i = 0; i < 8; i++) acc[i] = fmaf(xs[rg*8 + i][kkk], w, acc[i]);
        }
    }

    #pragma unroll
    for (int i = 0; i < 8; i++) {
        const int bt = row0 + rg*8 + i;
        if (c < 16) {
            const float z = acc[i] + ba[c];
            g_alpha[(size_t)bt*HHN + c] = 1.f / (1.f + expf(-z));
        } else {
            const int h = c - 16;
            const float z = acc[i] + bbv[h];
            const float sp = fmaxf(z, 0.f) + log1pf(expf(-fabsf(z)));
            g_beta[(size_t)bt*HHN + h] = sp * 0.088388347648318447f;
        }
    }
}

// ---------------------------------------------------------------------------
// l2norm of q,k rows + fused kq[bt,h] = dot(q_norm, k_norm). Warp per row.
// ---------------------------------------------------------------------------
__global__ __launch_bounds__(256)
void gdn_l2norm_kernel() {
    const int gw   = (blockIdx.x * 256 + threadIdx.x) >> 5;
    const int lane = threadIdx.x & 31;

    float4* pq = reinterpret_cast<float4*>(g_q) + (size_t)gw*32 + lane;
    float4* pk = reinterpret_cast<float4*>(g_k) + (size_t)gw*32 + lane;
    float4 vq = *pq;
    float4 vk = *pk;

    float sq = vq.x*vq.x + vq.y*vq.y + vq.z*vq.z + vq.w*vq.w;
    float sk = vk.x*vk.x + vk.y*vk.y + vk.z*vk.z + vk.w*vk.w;
    #pragma unroll
    for (int o = 16; o; o >>= 1) {
        sq += __shfl_xor_sync(0xffffffffu, sq, o);
        sk += __shfl_xor_sync(0xffffffffu, sk, o);
    }
    const float iq = 1.0f / fmaxf(sqrtf(sq), 1e-12f);
    const float ik = 1.0f / fmaxf(sqrtf(sk), 1e-12f);
    vq.x *= iq; vq.y *= iq; vq.z *= iq; vq.w *= iq;
    vk.x *= ik; vk.y *= ik; vk.z *= ik; vk.w *= ik;
    *pq = vq;
    *pk = vk;

    float d = vq.x*vk.x + vq.y*vk.y + vq.z*vk.z + vq.w*vk.w;
    #pragma unroll
    for (int o = 16; o; o >>= 1) d += __shfl_xor_sync(0xffffffffu, d, o);
    if (lane == 0) g_kq[gw] = d;
}

// ---------------------------------------------------------------------------
// Gated delta-rule scan v4:
//  - CTA = 128 thr (4 warps) covers 16 v-rows; grid (8,16,2) = 256 CTAs.
//  - k/q staged ONCE per CTA per step via 3-buffer cp.async ring, 1 bar/step.
//  - thread = 1 v-row x 16 k (f32x2); warp = 4v x 8kg -> 3-shfl reductions.
//  - o_t = a*(S_{t-1} q_t) + u*(k_t . q_t): predk/predq reduce concurrently,
//    kq precomputed -> o off the S critical path.
// ---------------------------------------------------------------------------
__device__ __forceinline__ ull f2fma(ull a, ull b, ull c) {
    ull d; asm("fma.rn.f32x2 %0, %1, %2, %3;" : "=l"(d) : "l"(a), "l"(b), "l"(c)); return d;
}
__device__ __forceinline__ ull f2mul(ull a, ull b) {
    ull d; asm("mul.rn.f32x2 %0, %1, %2;" : "=l"(d) : "l"(a), "l"(b)); return d;
}
__device__ __forceinline__ ull f2add(ull a, ull b) {
    ull d; asm("add.rn.f32x2 %0, %1, %2;" : "=l"(d) : "l"(a), "l"(b)); return d;
}
__device__ __forceinline__ ull f2pack(float lo, float hi) {
    ull d; asm("mov.b64 %0, {%1, %2};" : "=l"(d) : "f"(lo), "f"(hi)); return d;
}
__device__ __forceinline__ float f2hsum(ull a) {
    float lo, hi; asm("mov.b64 {%0, %1}, %2;" : "=f"(lo), "=f"(hi) : "l"(a)); return lo + hi;
}

#define SLC 20   // floats per kg slice in smem (16 data + 4 pad -> 80B stride)

__global__ __launch_bounds__(128, 2)
void gdn_scan_kernel(float* __restrict__ out) {
    __shared__ __align__(16) float kbuf[3][8*SLC];
    __shared__ __align__(16) float qbuf[3][8*SLC];

    const int b    = blockIdx.z;
    const int h    = blockIdx.y;
    const int tid  = threadIdx.x;
    const int w    = tid >> 5;
    const int lane = tid & 31;
    const int vi   = lane >> 3;        // 0..3
    const int kg   = lane & 7;         // 0..7  -> 16 k each
    const int vrow = blockIdx.x*16 + w*4 + vi;

    const float* krow = g_k     + (size_t)b*TT*HK + h*KKD;
    const float* qrow = g_q     + (size_t)b*TT*HK + h*KKD;
    const float* vp   = g_v     + (size_t)b*TT*HK + h*VVD + vrow;
    const float* ap   = g_alpha + (size_t)b*TT*HHN + h;
    const float* bp   = g_beta  + (size_t)b*TT*HHN + h;
    const float* kqp  = g_kq    + (size_t)b*TT*HHN + h;
    float*       op   = out     + (size_t)b*TT*HK + h*VVD + vrow;

    // staging: 64 chunks (k 32 + q 32); threads 0..63 issue, all commit
    const int sc   = tid & 31;                  // chunk id within tensor
    const bool isq = (tid >= 32);
    const bool act = (tid < 64);
    const float* srow = isq ? qrow : krow;

    auto stage = [&](int t, int s) {
        if (act) {
            const float* src = srow + (size_t)t*HK + sc*4;
            float* dst = (isq ? qbuf[s] : kbuf[s]) + (sc >> 2)*SLC + (sc & 3)*4;
            cp16(smem_u32(dst), src);
        }
        CP_COMMIT();
    };

    stage(0, 0);
    stage(1, 1);

    // scalar 2-ahead prefetch pipeline
    float vA = vp[0],  vB = vp[HK],   vC;
    float aA = ap[0],  aB = ap[HHN],  aC;
    float bA = bp[0],  bB = bp[HHN],  bC;
    float cA = kqp[0], cB = kqp[HHN], cC;

    ull S[8];
    #pragma unroll
    for (int i = 0; i < 8; i++) S[i] = 0;

    union F4U { float4 f; ull u[2]; };

    for (int t = 0; t < TT; ++t) {
        asm volatile("cp.async.wait_group 1;" ::: "memory");
        __syncthreads();
        const int s = t % 3;
        if (t + 2 < TT) stage(t + 2, (t + 2) % 3); else CP_COMMIT();

        // load this thread's k/q slices (16 floats each) from smem
        const float4* k4 = (const float4*)(kbuf[s] + kg*SLC);
        const float4* q4 = (const float4*)(qbuf[s] + kg*SLC);
        ull K[8], Q[8];
        #pragma unroll
        for (int j = 0; j < 4; j++) {
            F4U a; a.f = k4[j]; K[2*j] = a.u[0]; K[2*j+1] = a.u[1];
            F4U c; c.f = q4[j]; Q[2*j] = c.u[0]; Q[2*j+1] = c.u[1];
        }

        // prefetch scalars for t+2
        if (t + 2 < TT) {
            vC = vp[(size_t)(t+2)*HK];
            aC = ap[(size_t)(t+2)*HHN];
            bC = bp[(size_t)(t+2)*HHN];
            cC = kqp[(size_t)(t+2)*HHN];
        }

        // predk = S.k, predq = S.q (pre-update state), concurrent reductions
        ull pk0 = f2mul(S[0], K[0]), pk1 = f2mul(S[1], K[1]);
        ull pq0 = f2mul(S[0], Q[0]), pq1 = f2mul(S[1], Q[1]);
        pk0 = f2fma(S[2], K[2], pk0); pk1 = f2fma(S[3], K[3], pk1);
        pq0 = f2fma(S[2], Q[2], pq0); pq1 = f2fma(S[3], Q[3], pq1);
        pk0 = f2fma(S[4], K[4], pk0); pk1 = f2fma(S[5], K[5], pk1);
        pq0 = f2fma(S[4], Q[4], pq0); pq1 = f2fma(S[5], Q[5], pq1);
        pk0 = f2fma(S[6], K[6], pk0); pk1 = f2fma(S[7], K[7], pk1);
        pq0 = f2fma(S[6], Q[6], pq0); pq1 = f2fma(S[7], Q[7], pq1);
        float predk = f2hsum(f2add(pk0, pk1));
        float predq = f2hsum(f2add(pq0, pq1));
        #pragma unroll
        for (int o = 1; o <= 4; o <<= 1) {
            predk += __shfl_xor_sync(0xffffffffu, predk, o);
            predq += __shfl_xor_sync(0xffffffffu, predq, o);
        }

        const float u = bA * (vA - aA * predk);
        const float o = fmaf(u, cA, aA * predq);
        if (kg == 0) op[(size_t)t*HK] = o;

        const ull a2 = f2pack(aA, aA);
        const ull u2 = f2pack(u, u);
        #pragma unroll
        for (int i = 0; i < 8; i++)
            S[i] = f2fma(u2, K[i], f2mul(a2, S[i]));

        vA = vB; vB = vC;
        aA = aB; aB = aC;
        bA = bB; bB = bC;
        cA = cB; cB = cC;
    }
}

// ---------------------------------------------------------------------------
extern "C" void kernel_launch(void* const* d_in, const int* in_sizes, int n_in,
                              void* d_out, int out_size) {
    const float* x   = (const float*)d_in[0];
    const float* Wq  = (const float*)d_in[1];
    const float* Wk  = (const float*)d_in[2];
    const float* Wv  = (const float*)d_in[3];
    const float* Wa  = (const float*)d_in[4];
    const float* ba  = (const float*)d_in[5];
    const float* Wb  = (const float*)d_in[6];
    const float* bbv = (const float*)d_in[7];
    float* out = (float*)d_out;

    __half *xh, *wqh, *wkh, *wvh;
    cudaGetSymbolAddress((void**)&xh,  g_xh);
    cudaGetSymbolAddress((void**)&wqh, g_wqh);
    cudaGetSymbolAddress((void**)&wkh, g_wkh);
    cudaGetSymbolAddress((void**)&wvh, g_wvh);

    cudaFuncSetAttribute(gdn_proj_gemm, cudaFuncAttributeMaxDynamicSharedMemorySize, GEMM_SMEM);

    gdn_convh_kernel<<<1024, 256>>>(x,  (uint4*)xh,  BT*DD/8);
    gdn_convh_kernel<<<512,  256>>>(Wq, (uint4*)wqh, HK*DD/8);
    gdn_convh_kernel<<<512,  256>>>(Wk, (uint4*)wkh, HK*DD/8);
    gdn_convh_kernel<<<512,  256>>>(Wv, (uint4*)wvh, HK*DD/8);

    gdn_proj_gemm<<<dim3(HK/128, BT/128, 3), 256, GEMM_SMEM>>>();  // (16, 32, 3)
    gdn_ab_kernel<<<BT/64, 256>>>(x, Wa, ba, Wb, bbv);
    gdn_l2norm_kernel<<<(BT*HHN)/8, 256>>>();
    gdn_scan_kernel<<<dim3(8, HHN, BB), 128>>>(out);
}

// round 10
// speedup vs baseline: 1.6532x; 1.2236x over previous
#include <cuda_runtime.h>
#include <cuda_fp16.h>
#include <math.h>
#include <stdint.h>

typedef unsigned long long ull;

// Problem dims (fixed)
#define BB 2
#define TT 2048
#define DD 2048
#define HHN 16
#define KKD 128
#define VVD 128
#define BT  (BB*TT)     // 4096
#define HK  (HHN*KKD)   // 2048
#define NG  (TT/2)      // 1024 two-step groups

// Scratch (device globals: no allocation allowed)
__device__ float g_q[BT*HK];
__device__ float g_k[BT*HK];
__device__ float g_v[BT*HK];
__device__ float g_alpha[BT*HHN];
__device__ float g_beta[BT*HHN];
__device__ float g_kq[BT*HHN];          // k_t . q_t
__device__ float g_kk[BB*NG*HHN];       // k_{2g} . k_{2g+1}
__device__ float g_kq12[BB*NG*HHN];     // k_{2g} . q_{2g+1}
__device__ __half g_xh[BT*DD];          // fp16 X
__device__ __half g_wqh[HK*DD];         // fp16 weights
__device__ __half g_wkh[HK*DD];
__device__ __half g_wvh[HK*DD];

// ---------------------------------------------------------------------------
// helpers
// ---------------------------------------------------------------------------
__device__ __forceinline__ uint32_t smem_u32(const void* p) {
    uint32_t a;
    asm("{ .reg .u64 t; cvta.to.shared.u64 t, %1; cvt.u32.u64 %0, t; }" : "=r"(a) : "l"(p));
    return a;
}
__device__ __forceinline__ void cp16(uint32_t dst, const void* src) {
    asm volatile("cp.async.cg.shared.global [%0], [%1], 16;" :: "r"(dst), "l"(src));
}
#define CP_COMMIT() asm volatile("cp.async.commit_group;" ::: "memory")

__device__ __forceinline__ uint32_t h2_bits(__half2 h) {
    union { __half2 h; uint32_t u; } cv; cv.h = h; return cv.u;
}

__device__ __forceinline__ void mma_f16(float* d, const uint32_t* a, const uint32_t* b) {
    asm volatile("mma.sync.aligned.m16n8k16.row.col.f32.f16.f16.f32 "
        "{%0,%1,%2,%3}, {%4,%5,%6,%7}, {%8,%9}, {%0,%1,%2,%3};"
        : "+f"(d[0]), "+f"(d[1]), "+f"(d[2]), "+f"(d[3])
        : "r"(a[0]), "r"(a[1]), "r"(a[2]), "r"(a[3]), "r"(b[0]), "r"(b[1]));
}

// ---------------------------------------------------------------------------
// f32 -> fp16 conversion pre-pass
// ---------------------------------------------------------------------------
__global__ __launch_bounds__(256)
void gdn_convh_kernel(const float* __restrict__ src, uint4* __restrict__ dst, int n8) {
    int i = blockIdx.x * 256 + threadIdx.x;
    const int stride = gridDim.x * 256;
    const float4* s = (const float4*)src;
    for (; i < n8; i += stride) {
        float4 a = s[2*i], b = s[2*i+1];
        uint4 o;
        o.x = h2_bits(__floats2half2_rn(a.x, a.y));
        o.y = h2_bits(__floats2half2_rn(a.z, a.w));
        o.z = h2_bits(__floats2half2_rn(b.x, b.y));
        o.w = h2_bits(__floats2half2_rn(b.z, b.w));
        dst[i] = o;
    }
}

// ---------------------------------------------------------------------------
// Projection GEMM (fp16 m16n8k16): C[4096,2048] = X @ W^T.
// BM=BN=128, BK=32 halves, 3-stage cp.async ring, 256 thr, warp tile 32x64.
// ---------------------------------------------------------------------------
#define RS   40
#define STG_H (128*RS)
#define STG_BYTES (STG_H*2)
#define GEMM_SMEM (3*2*STG_BYTES)

__global__ __launch_bounds__(256, 2)
void gdn_proj_gemm() {
    extern __shared__ __align__(16) __half hsm[];

    const __half* X = g_xh;
    const __half* W; float* C;
    if (blockIdx.z == 0)      { W = g_wqh; C = g_q; }
    else if (blockIdx.z == 1) { W = g_wkh; C = g_k; }
    else                      { W = g_wvh; C = g_v; }

    const int tid  = threadIdx.x;
    const int lane = tid & 31;
    const int wid  = tid >> 5;
    const int wm   = wid >> 1;
    const int wn   = wid & 1;
    const int g    = lane >> 2;
    const int tig  = lane & 3;

    const int rowA = blockIdx.y * 128;
    const int rowB = blockIdx.x * 128;

    const int lrow = tid >> 2;
    const int lcb  = (tid & 3) * 16;
    const int lch  = (tid & 3) * 8;

    const uint32_t sb = smem_u32(hsm);

    auto load_stage = [&](int kt) {
        const int s = kt % 3;
        const uint32_t abase = sb + s * 2 * STG_BYTES;
        const uint32_t bbase = abase + STG_BYTES;
        const int k0 = kt * 32;
        cp16(abase + (uint32_t)lrow * 80 + lcb,        X + (size_t)(rowA + lrow) * DD + k0 + lch);
        cp16(abase + (uint32_t)(lrow + 64) * 80 + lcb, X + (size_t)(rowA + lrow + 64) * DD + k0 + lch);
        cp16(bbase + (uint32_t)lrow * 80 + lcb,        W + (size_t)(rowB + lrow) * DD + k0 + lch);
        cp16(bbase + (uint32_t)(lrow + 64) * 80 + lcb, W + (size_t)(rowB + lrow + 64) * DD + k0 + lch);
        CP_COMMIT();
    };

    float acc[2][8][4];
    #pragma unroll
    for (int i = 0; i < 2; i++)
        #pragma unroll
        for (int j = 0; j < 8; j++)
            #pragma unroll
            for (int l = 0; l < 4; l++) acc[i][j][l] = 0.f;

    load_stage(0);
    load_stage(1);

    const int KT = DD / 32;   // 64
    for (int kt = 0; kt < KT; ++kt) {
        asm volatile("cp.async.wait_group 1;" ::: "memory");
        __syncthreads();

        if (kt + 2 < KT) load_stage(kt + 2); else CP_COMMIT();

        const int s = kt % 3;
        const uint32_t* As32 = (const uint32_t*)(hsm + (size_t)s * 2 * STG_H);
        const uint32_t* Bs32 = As32 + STG_H / 2;

        #pragma unroll
        for (int kk2 = 0; kk2 < 16; kk2 += 8) {
            uint32_t afr[2][4], bfr[8][2];
            #pragma unroll
            for (int mt = 0; mt < 2; mt++) {
                const int rb = wm*32 + mt*16;
                afr[mt][0] = As32[(rb + g    )*20 + kk2 + tig    ];
                afr[mt][1] = As32[(rb + g + 8)*20 + kk2 + tig    ];
                afr[mt][2] = As32[(rb + g    )*20 + kk2 + tig + 4];
                afr[mt][3] = As32[(rb + g + 8)*20 + kk2 + tig + 4];
            }
            #pragma unroll
            for (int nt = 0; nt < 8; nt++) {
                const int cb = wn*64 + nt*8;
                bfr[nt][0] = Bs32[(cb + g)*20 + kk2 + tig    ];
                bfr[nt][1] = Bs32[(cb + g)*20 + kk2 + tig + 4];
            }
            #pragma unroll
            for (int mt = 0; mt < 2; mt++)
                #pragma unroll
                for (int nt = 0; nt < 8; nt++)
                    mma_f16(acc[mt][nt], afr[mt], bfr[nt]);
        }
        __syncthreads();
    }

    #pragma unroll
    for (int mt = 0; mt < 2; mt++) {
        #pragma unroll
        for (int nt = 0; nt < 8; nt++) {
            const int r  = rowA + wm*32 + mt*16 + g;
            const int cc = rowB + wn*64 + nt*8 + tig*2;
            *(float2*)(C + (size_t)r*HK + cc)       = make_float2(acc[mt][nt][0], acc[mt][nt][1]);
            *(float2*)(C + (size_t)(r + 8)*HK + cc) = make_float2(acc[mt][nt][2], acc[mt][nt][3]);
        }
    }
}

// ---------------------------------------------------------------------------
// alpha/beta: [4096,32] = X @ [Wa;Wb]^T, then sigmoid / softplus*K^-0.5.
// ---------------------------------------------------------------------------
__global__ __launch_bounds__(256)
void gdn_ab_kernel(const float* __restrict__ X,
                   const float* __restrict__ Wa, const float* __restrict__ ba,
                   const float* __restrict__ Wb, const float* __restrict__ bbv) {
    __shared__ float xs[64][36];
    __shared__ float ws[32][33];
    const int tid  = threadIdx.x;
    const int row0 = blockIdx.x * 64;
    const int c    = tid & 31;
    const int rg   = tid >> 5;

    float acc[8];
    #pragma unroll
    for (int i = 0; i < 8; i++) acc[i] = 0.f;

    for (int k0 = 0; k0 < DD; k0 += 32) {
        __syncthreads();
        #pragma unroll
        for (int i = 0; i < 2; i++) {
            const int f = tid + i*256;
            const int r = f >> 3, c4 = (f & 7)*4;
            float4 val = *(const float4*)(X + (size_t)(row0 + r)*DD + k0 + c4);
            *(float4*)&xs[r][c4] = val;
        }
        #pragma unroll
        for (int i = 0; i < 4; i++) {
            const int f = tid + i*256;
            const int o = f >> 5, kkk = f & 31;
            const float* wr = (o < 16) ? (Wa + (size_t)o*DD) : (Wb + (size_t)(o - 16)*DD);
            ws[kkk][o] = wr[k0 + kkk];
        }
        __syncthreads();
        #pragma unroll 4
        for (int kkk = 0; kkk < 32; ++kkk) {
            const float w = ws[kkk][c];
            #pragma unroll
            for (int i = 0; i < 8; i++) acc[i] = fmaf(xs[rg*8 + i][kkk], w, acc[i]);
        }
    }

    #pragma unroll
    for (int i = 0; i < 8; i++) {
        const int bt = row0 + rg*8 + i;
        if (c < 16) {
            const float z = acc[i] + ba[c];
            g_alpha[(size_t)bt*HHN + c] = 1.f / (1.f + expf(-z));
        } else {
            const int h = c - 16;
            const float z = acc[i] + bbv[h];
            const float sp = fmaxf(z, 0.f) + log1pf(expf(-fabsf(z)));
            g_beta[(size_t)bt*HHN + h] = sp * 0.088388347648318447f;
        }
    }
}

// ---------------------------------------------------------------------------
// l2norm of q,k rows + fused kq[bt,h] = dot(q_norm, k_norm). Warp per row.
// ---------------------------------------------------------------------------
__global__ __launch_bounds__(256)
void gdn_l2norm_kernel() {
    const int gw   = (blockIdx.x * 256 + threadIdx.x) >> 5;
    const int lane = threadIdx.x & 31;

    float4* pq = reinterpret_cast<float4*>(g_q) + (size_t)gw*32 + lane;
    float4* pk = reinterpret_cast<float4*>(g_k) + (size_t)gw*32 + lane;
    float4 vq = *pq;
    float4 vk = *pk;

    float sq = vq.x*vq.x + vq.y*vq.y + vq.z*vq.z + vq.w*vq.w;
    float sk = vk.x*vk.x + vk.y*vk.y + vk.z*vk.z + vk.w*vk.w;
    #pragma unroll
    for (int o = 16; o; o >>= 1) {
        sq += __shfl_xor_sync(0xffffffffu, sq, o);
        sk += __shfl_xor_sync(0xffffffffu, sk, o);
    }
    const float iq = 1.0f / fmaxf(sqrtf(sq), 1e-12f);
    const float ik = 1.0f / fmaxf(sqrtf(sk), 1e-12f);
    vq.x *= iq; vq.y *= iq; vq.z *= iq; vq.w *= iq;
    vk.x *= ik; vk.y *= ik; vk.z *= ik; vk.w *= ik;
    *pq = vq;
    *pk = vk;

    float d = vq.x*vk.x + vq.y*vk.y + vq.z*vk.z + vq.w*vk.w;
    #pragma unroll
    for (int o = 16; o; o >>= 1) d += __shfl_xor_sync(0xffffffffu, d, o);
    if (lane == 0) g_kq[gw] = d;
}

// ---------------------------------------------------------------------------
// Cross-dot precompute: for each (b, pair p, h):
//   g_kk  = k_{2p} . k_{2p+1},  g_kq12 = k_{2p} . q_{2p+1}
// Warp per (b,p,h). MUST run after l2norm (normalized vectors).
// ---------------------------------------------------------------------------
__global__ __launch_bounds__(256)
void gdn_cross_kernel() {
    const int gw   = (blockIdx.x * 256 + threadIdx.x) >> 5;  // 0..BB*NG*HHN-1
    const int lane = threadIdx.x & 31;
    const int h = gw & (HHN-1);
    const int p = (gw >> 4) & (NG-1);
    const int b = gw >> 14;

    const float4* k1 = (const float4*)(g_k + (size_t)(b*TT + 2*p    )*HK + h*KKD);
    const float4* k2 = (const float4*)(g_k + (size_t)(b*TT + 2*p + 1)*HK + h*KKD);
    const float4* q2 = (const float4*)(g_q + (size_t)(b*TT + 2*p + 1)*HK + h*KKD);
    float4 a = k1[lane], c = k2[lane], d = q2[lane];

    float dkk = a.x*c.x + a.y*c.y + a.z*c.z + a.w*c.w;
    float dkq = a.x*d.x + a.y*d.y + a.z*d.z + a.w*d.w;
    #pragma unroll
    for (int o = 16; o; o >>= 1) {
        dkk += __shfl_xor_sync(0xffffffffu, dkk, o);
        dkq += __shfl_xor_sync(0xffffffffu, dkq, o);
    }
    if (lane == 0) { g_kk[gw] = dkk; g_kq12[gw] = dkq; }
}

// ---------------------------------------------------------------------------
// Gated delta-rule scan v5: 2-step fused recurrence.
//  - CTA = 256 thr (8 warps) = 32 v-rows; grid (4,16,2) = 128 CTAs (1/SM).
//  - Per 2-step group: P1=S.k1, P2=S.k2, R1=S.q1, R2=S.q2 reduce CONCURRENTLY
//    on pre-update S (one shuffle cascade per 2 steps).
//      u1 = b1(v1 - a1 P1);             o1 = a1 R1 + u1 kq1
//      u2 = b2(v2 - a2(a1 P2 + u1 dkk)); o2 = a2(a1 R2 + u1 dkq12) + u2 kq2
//      S  = (a1 a2) S + (a2 u1) k1 + u2 k2
//  - k/q pairs staged via 3-group cp.async ring; 1 barrier per 2 steps.
// ---------------------------------------------------------------------------
__device__ __forceinline__ ull f2fma(ull a, ull b, ull c) {
    ull d; asm("fma.rn.f32x2 %0, %1, %2, %3;" : "=l"(d) : "l"(a), "l"(b), "l"(c)); return d;
}
__device__ __forceinline__ ull f2mul(ull a, ull b) {
    ull d; asm("mul.rn.f32x2 %0, %1, %2;" : "=l"(d) : "l"(a), "l"(b)); return d;
}
__device__ __forceinline__ ull f2add(ull a, ull b) {
    ull d; asm("add.rn.f32x2 %0, %1, %2;" : "=l"(d) : "l"(a), "l"(b)); return d;
}
__device__ __forceinline__ ull f2pack(float lo, float hi) {
    ull d; asm("mov.b64 %0, {%1, %2};" : "=l"(d) : "f"(lo), "f"(hi)); return d;
}
__device__ __forceinline__ float f2hsum(ull a) {
    float lo, hi; asm("mov.b64 {%0, %1}, %2;" : "=f"(lo), "=f"(hi) : "l"(a)); return lo + hi;
}

#define SLC 20   // floats per kg slice (16 data + 4 pad -> 80B stride)

__global__ __launch_bounds__(256, 1)
void gdn_scan_kernel(float* __restrict__ out) {
    __shared__ __align__(16) float kbuf[3][2][8*SLC];
    __shared__ __align__(16) float qbuf[3][2][8*SLC];

    const int b    = blockIdx.z;
    const int h    = blockIdx.y;
    const int tid  = threadIdx.x;
    const int w    = tid >> 5;
    const int lane = tid & 31;
    const int vi   = lane >> 3;        // 0..3
    const int kg   = lane & 7;         // 0..7 -> 16 k each
    const int vrow = blockIdx.x*32 + w*4 + vi;

    const float* krow  = g_k     + (size_t)b*TT*HK + h*KKD;
    const float* qrow  = g_q     + (size_t)b*TT*HK + h*KKD;
    const float* vp    = g_v     + (size_t)b*TT*HK + h*VVD + vrow;
    const float* ap    = g_alpha + (size_t)b*TT*HHN + h;
    const float* bp    = g_beta  + (size_t)b*TT*HHN + h;
    const float* kqp   = g_kq    + (size_t)b*TT*HHN + h;
    const float* kkp   = g_kk    + (size_t)b*NG*HHN + h;
    const float* x12p  = g_kq12  + (size_t)b*NG*HHN + h;
    float*       op    = out     + (size_t)b*TT*HK + h*VVD + vrow;

    // staging: 4 rows (k even/odd, q even/odd) x 32 chunks = 128; tid<128 active
    const int part = tid >> 5;          // 0..3 when tid<128
    const int sc   = tid & 31;

    auto stage = [&](int g, int s) {
        if (tid < 128) {
            const float* src = ((part < 2) ? krow : qrow) + (size_t)(2*g + (part & 1))*HK + sc*4;
            float* dst = ((part < 2) ? kbuf[s][part & 1] : qbuf[s][part & 1])
                         + (sc >> 2)*SLC + (sc & 3)*4;
            cp16(smem_u32(dst), src);
        }
        CP_COMMIT();
    };

    stage(0, 0);
    stage(1, 1);

    // scalar prefetch, 1 group ahead
    float v1A = vp[0],  v2A = vp[HK];
    float a1A = ap[0],  a2A = ap[HHN];
    float b1A = bp[0],  b2A = bp[HHN];
    float q1A = kqp[0], q2A = kqp[HHN];
    float kkA = kkp[0], xA  = x12p[0];

    ull S[8];
    #pragma unroll
    for (int i = 0; i < 8; i++) S[i] = 0;

    union F4U { float4 f; ull u[2]; };

    for (int g = 0; g < NG; ++g) {
        asm volatile("cp.async.wait_group 1;" ::: "memory");
        __syncthreads();
        const int s = g % 3;
        if (g + 2 < NG) stage(g + 2, (g + 2) % 3); else CP_COMMIT();

        // load K1,K2,Q1,Q2 slices (16 floats each) from smem
        const float4* k14 = (const float4*)(kbuf[s][0] + kg*SLC);
        const float4* k24 = (const float4*)(kbuf[s][1] + kg*SLC);
        const float4* q14 = (const float4*)(qbuf[s][0] + kg*SLC);
        const float4* q24 = (const float4*)(qbuf[s][1] + kg*SLC);
        ull K1[8], K2[8], Q1[8], Q2[8];
        #pragma unroll
        for (int j = 0; j < 4; j++) {
            F4U t0; t0.f = k14[j]; K1[2*j] = t0.u[0]; K1[2*j+1] = t0.u[1];
            F4U t1; t1.f = k24[j]; K2[2*j] = t1.u[0]; K2[2*j+1] = t1.u[1];
            F4U t2; t2.f = q14[j]; Q1[2*j] = t2.u[0]; Q1[2*j+1] = t2.u[1];
            F4U t3; t3.f = q24[j]; Q2[2*j] = t3.u[0]; Q2[2*j+1] = t3.u[1];
        }

        // prefetch next group scalars (overlaps reductions)
        float v1B, v2B, a1B, a2B, b1B, b2B, q1B, q2B, kkB, xB;
        if (g + 1 < NG) {
            const size_t t0 = (size_t)(2*g + 2);
            v1B = vp[t0*HK];        v2B = vp[(t0+1)*HK];
            a1B = ap[t0*HHN];       a2B = ap[(t0+1)*HHN];
            b1B = bp[t0*HHN];       b2B = bp[(t0+1)*HHN];
            q1B = kqp[t0*HHN];      q2B = kqp[(t0+1)*HHN];
            kkB = kkp[(size_t)(g+1)*HHN];
            xB  = x12p[(size_t)(g+1)*HHN];
        }

        // 4 concurrent reductions on pre-update S (2 chains each)
        ull p1a = f2mul(S[0], K1[0]), p1b = f2mul(S[1], K1[1]);
        ull p2a = f2mul(S[0], K2[0]), p2b = f2mul(S[1], K2[1]);
        ull r1a = f2mul(S[0], Q1[0]), r1b = f2mul(S[1], Q1[1]);
        ull r2a = f2mul(S[0], Q2[0]), r2b = f2mul(S[1], Q2[1]);
        #pragma unroll
        for (int j = 1; j < 4; j++) {
            p1a = f2fma(S[2*j], K1[2*j], p1a); p1b = f2fma(S[2*j+1], K1[2*j+1], p1b);
            p2a = f2fma(S[2*j], K2[2*j], p2a); p2b = f2fma(S[2*j+1], K2[2*j+1], p2b);
            r1a = f2fma(S[2*j], Q1[2*j], r1a); r1b = f2fma(S[2*j+1], Q1[2*j+1], r1b);
            r2a = f2fma(S[2*j], Q2[2*j], r2a); r2b = f2fma(S[2*j+1], Q2[2*j+1], r2b);
        }
        float P1 = f2hsum(f2add(p1a, p1b));
        float P2 = f2hsum(f2add(p2a, p2b));
        float R1 = f2hsum(f2add(r1a, r1b));
        float R2 = f2hsum(f2add(r2a, r2b));
        #pragma unroll
        for (int o = 1; o <= 4; o <<= 1) {
            P1 += __shfl_xor_sync(0xffffffffu, P1, o);
            P2 += __shfl_xor_sync(0xffffffffu, P2, o);
            R1 += __shfl_xor_sync(0xffffffffu, R1, o);
            R2 += __shfl_xor_sync(0xffffffffu, R2, o);
        }

        // scalar 2-step recurrence
        const float u1 = b1A * (v1A - a1A * P1);
        const float o1 = fmaf(u1, q1A, a1A * R1);
        const float p2p = fmaf(u1, kkA, a1A * P2);
        const float u2 = b2A * (v2A - a2A * p2p);
        const float r2p = fmaf(u1, xA, a1A * R2);
        const float o2 = fmaf(u2, q2A, a2A * r2p);
        if (kg == 0) {
            op[(size_t)(2*g    )*HK] = o1;
            op[(size_t)(2*g + 1)*HK] = o2;
        }

        // fused S update: S = (a1 a2) S + (a2 u1) K1 + u2 K2
        const ull c0 = f2pack(a1A*a2A, a1A*a2A);
        const ull c1 = f2pack(a2A*u1,  a2A*u1);
        const ull c2 = f2pack(u2,      u2);
        #pragma unroll
        for (int i = 0; i < 8; i++)
            S[i] = f2fma(c2, K2[i], f2fma(c1, K1[i], f2mul(c0, S[i])));

        v1A = v1B; v2A = v2B; a1A = a1B; a2A = a2B; b1A = b1B; b2A = b2B;
        q1A = q1B; q2A = q2B; kkA = kkB; xA = xB;
    }
}

// ---------------------------------------------------------------------------
extern "C" void kernel_launch(void* const* d_in, const int* in_sizes, int n_in,
                              void* d_out, int out_size) {
    const float* x   = (const float*)d_in[0];
    const float* Wq  = (const float*)d_in[1];
    const float* Wk  = (const float*)d_in[2];
    const float* Wv  = (const float*)d_in[3];
    const float* Wa  = (const float*)d_in[4];
    const float* ba  = (const float*)d_in[5];
    const float* Wb  = (const float*)d_in[6];
    const float* bbv = (const float*)d_in[7];
    float* out = (float*)d_out;

    __half *xh, *wqh, *wkh, *wvh;
    cudaGetSymbolAddress((void**)&xh,  g_xh);
    cudaGetSymbolAddress((void**)&wqh, g_wqh);
    cudaGetSymbolAddress((void**)&wkh, g_wkh);
    cudaGetSymbolAddress((void**)&wvh, g_wvh);

    cudaFuncSetAttribute(gdn_proj_gemm, cudaFuncAttributeMaxDynamicSharedMemorySize, GEMM_SMEM);

    gdn_convh_kernel<<<1024, 256>>>(x,  (uint4*)xh,  BT*DD/8);
    gdn_convh_kernel<<<512,  256>>>(Wq, (uint4*)wqh, HK*DD/8);
    gdn_convh_kernel<<<512,  256>>>(Wk, (uint4*)wkh, HK*DD/8);
    gdn_convh_kernel<<<512,  256>>>(Wv, (uint4*)wvh, HK*DD/8);

    gdn_proj_gemm<<<dim3(HK/128, BT/128, 3), 256, GEMM_SMEM>>>();  // (16, 32, 3)
    gdn_ab_kernel<<<BT/64, 256>>>(x, Wa, ba, Wb, bbv);
    gdn_l2norm_kernel<<<(BT*HHN)/8, 256>>>();
    gdn_cross_kernel<<<(BB*NG*HHN)/8, 256>>>();
    gdn_scan_kernel<<<dim3(4, HHN, BB), 256>>>(out);
}

// round 11
// speedup vs baseline: 1.9922x; 1.2051x over previous
#include <cuda_runtime.h>
#include <cuda_fp16.h>
#include <math.h>
#include <stdint.h>

typedef unsigned long long ull;

// Problem dims (fixed)
#define BB 2
#define TT 2048
#define DD 2048
#define HHN 16
#define KKD 128
#define VVD 128
#define BT  (BB*TT)     // 4096
#define HK  (HHN*KKD)   // 2048
#define NG4 512         // 4-step groups

// Scratch (device globals: no allocation allowed)
__device__ float g_q[BT*HK];
__device__ float g_k[BT*HK];
__device__ float g_v[BT*HK];
__device__ float g_alpha[BT*HHN];
__device__ float g_beta[BT*HHN];
__device__ float g_kq[BT*HHN];              // k_t . q_t
__device__ float g_cd[BB*HHN*NG4*12];       // per group: K12,K13,K14,K23,K24,K34,X12,X13,X14,X23,X24,X34
__device__ __half g_xh[BT*DD];
__device__ __half g_wqh[HK*DD];
__device__ __half g_wkh[HK*DD];
__device__ __half g_wvh[HK*DD];

// ---------------------------------------------------------------------------
// helpers
// ---------------------------------------------------------------------------
__device__ __forceinline__ uint32_t smem_u32(const void* p) {
    uint32_t a;
    asm("{ .reg .u64 t; cvta.to.shared.u64 t, %1; cvt.u32.u64 %0, t; }" : "=r"(a) : "l"(p));
    return a;
}
__device__ __forceinline__ void cp16(uint32_t dst, const void* src) {
    asm volatile("cp.async.cg.shared.global [%0], [%1], 16;" :: "r"(dst), "l"(src));
}
#define CP_COMMIT() asm volatile("cp.async.commit_group;" ::: "memory")

__device__ __forceinline__ uint32_t h2_bits(__half2 h) {
    union { __half2 h; uint32_t u; } cv; cv.h = h; return cv.u;
}

__device__ __forceinline__ void mma_f16(float* d, const uint32_t* a, const uint32_t* b) {
    asm volatile("mma.sync.aligned.m16n8k16.row.col.f32.f16.f16.f32 "
        "{%0,%1,%2,%3}, {%4,%5,%6,%7}, {%8,%9}, {%0,%1,%2,%3};"
        : "+f"(d[0]), "+f"(d[1]), "+f"(d[2]), "+f"(d[3])
        : "r"(a[0]), "r"(a[1]), "r"(a[2]), "r"(a[3]), "r"(b[0]), "r"(b[1]));
}

#define LDSM_X4(r0, r1, r2, r3, addr) \
    asm volatile("ldmatrix.sync.aligned.m8n8.x4.shared.b16 {%0,%1,%2,%3}, [%4];" \
        : "=r"(r0), "=r"(r1), "=r"(r2), "=r"(r3) : "r"(addr))

// ---------------------------------------------------------------------------
// f32 -> fp16 conversion pre-pass
// ---------------------------------------------------------------------------
__global__ __launch_bounds__(256)
void gdn_convh_kernel(const float* __restrict__ src, uint4* __restrict__ dst, int n8) {
    int i = blockIdx.x * 256 + threadIdx.x;
    const int stride = gridDim.x * 256;
    const float4* s = (const float4*)src;
    for (; i < n8; i += stride) {
        float4 a = s[2*i], b = s[2*i+1];
        uint4 o;
        o.x = h2_bits(__floats2half2_rn(a.x, a.y));
        o.y = h2_bits(__floats2half2_rn(a.z, a.w));
        o.z = h2_bits(__floats2half2_rn(b.x, b.y));
        o.w = h2_bits(__floats2half2_rn(b.z, b.w));
        dst[i] = o;
    }
}

// ---------------------------------------------------------------------------
// Projection GEMM (fp16 m16n8k16 + ldmatrix.x4): C[4096,2048] = X @ W^T.
// BM=BN=128, BK=32 halves, 3-stage cp.async ring, 256 thr, warp tile 32x64.
// Padded 80B smem rows; ldmatrix lane-addressing derived for that stride
// (row stride 20 words -> 8 rows of a tile land in 8 distinct banks).
// ---------------------------------------------------------------------------
#define RS   40
#define STG_H (128*RS)
#define STG_BYTES (STG_H*2)
#define GEMM_SMEM (3*2*STG_BYTES)

__global__ __launch_bounds__(256, 2)
void gdn_proj_gemm() {
    extern __shared__ __align__(16) __half hsm[];

    const __half* X = g_xh;
    const __half* W; float* C;
    if (blockIdx.z == 0)      { W = g_wqh; C = g_q; }
    else if (blockIdx.z == 1) { W = g_wkh; C = g_k; }
    else                      { W = g_wvh; C = g_v; }

    const int tid  = threadIdx.x;
    const int lane = tid & 31;
    const int wid  = tid >> 5;
    const int wm   = wid >> 1;
    const int wn   = wid & 1;
    const int g    = lane >> 2;
    const int tig  = lane & 3;

    const int rowA = blockIdx.y * 128;
    const int rowB = blockIdx.x * 128;

    const int lrow = tid >> 2;
    const int lcb  = (tid & 3) * 16;
    const int lch  = (tid & 3) * 8;

    const uint32_t sb = smem_u32(hsm);

    // ldmatrix per-lane offsets (bytes within a stage)
    const int l8 = lane & 7;
    // A: t0 r+0/c0, t1 r+8/c0, t2 r+0/c16B, t3 r+8/c16B
    const int aradd = ((lane >> 3) & 1) * 8;
    const int acadd = ((lane >> 4) & 1) * 16;
    uint32_t aoff[2];
    #pragma unroll
    for (int mt = 0; mt < 2; mt++)
        aoff[mt] = (uint32_t)(wm*32 + mt*16 + aradd + l8) * 80 + acadd;
    // B: t0 n+0/c0, t1 n+0/c16B, t2 n+8/c0, t3 n+8/c16B
    const int bradd = ((lane >> 4) & 1) * 8;
    const int bcadd = ((lane >> 3) & 1) * 16;
    uint32_t boff[4];
    #pragma unroll
    for (int p = 0; p < 4; p++)
        boff[p] = (uint32_t)(wn*64 + p*16 + bradd + l8) * 80 + bcadd;

    auto load_stage = [&](int kt) {
        const int s = kt % 3;
        const uint32_t abase = sb + s * 2 * STG_BYTES;
        const uint32_t bbase = abase + STG_BYTES;
        const int k0 = kt * 32;
        cp16(abase + (uint32_t)lrow * 80 + lcb,        X + (size_t)(rowA + lrow) * DD + k0 + lch);
        cp16(abase + (uint32_t)(lrow + 64) * 80 + lcb, X + (size_t)(rowA + lrow + 64) * DD + k0 + lch);
        cp16(bbase + (uint32_t)lrow * 80 + lcb,        W + (size_t)(rowB + lrow) * DD + k0 + lch);
        cp16(bbase + (uint32_t)(lrow + 64) * 80 + lcb, W + (size_t)(rowB + lrow + 64) * DD + k0 + lch);
        CP_COMMIT();
    };

    float acc[2][8][4];
    #pragma unroll
    for (int i = 0; i < 2; i++)
        #pragma unroll
        for (int j = 0; j < 8; j++)
            #pragma unroll
            for (int l = 0; l < 4; l++) acc[i][j][l] = 0.f;

    load_stage(0);
    load_stage(1);

    const int KT = DD / 32;   // 64
    for (int kt = 0; kt < KT; ++kt) {
        asm volatile("cp.async.wait_group 1;" ::: "memory");
        __syncthreads();

        if (kt + 2 < KT) load_stage(kt + 2); else CP_COMMIT();

        const int s = kt % 3;
        const uint32_t abase = sb + s * 2 * STG_BYTES;
        const uint32_t bbase = abase + STG_BYTES;

        #pragma unroll
        for (int kk2 = 0; kk2 < 16; kk2 += 8) {
            const uint32_t kb = kk2 * 4;   // byte offset for this k16 step
            uint32_t afr[2][4], bfr[8][2];
            LDSM_X4(afr[0][0], afr[0][1], afr[0][2], afr[0][3], abase + aoff[0] + kb);
            LDSM_X4(afr[1][0], afr[1][1], afr[1][2], afr[1][3], abase + aoff[1] + kb);
            #pragma unroll
            for (int p = 0; p < 4; p++)
                LDSM_X4(bfr[2*p][0], bfr[2*p][1], bfr[2*p+1][0], bfr[2*p+1][1],
                        bbase + boff[p] + kb);
            #pragma unroll
            for (int mt = 0; mt < 2; mt++)
                #pragma unroll
                for (int nt = 0; nt < 8; nt++)
                    mma_f16(acc[mt][nt], afr[mt], bfr[nt]);
        }
        __syncthreads();
    }

    #pragma unroll
    for (int mt = 0; mt < 2; mt++) {
        #pragma unroll
        for (int nt = 0; nt < 8; nt++) {
            const int r  = rowA + wm*32 + mt*16 + g;
            const int cc = rowB + wn*64 + nt*8 + tig*2;
            *(float2*)(C + (size_t)r*HK + cc)       = make_float2(acc[mt][nt][0], acc[mt][nt][1]);
            *(float2*)(C + (size_t)(r + 8)*HK + cc) = make_float2(acc[mt][nt][2], acc[mt][nt][3]);
        }
    }
}

// ---------------------------------------------------------------------------
// alpha/beta: [4096,32] = X @ [Wa;Wb]^T, then sigmoid / softplus*K^-0.5.
// ---------------------------------------------------------------------------
__global__ __launch_bounds__(256)
void gdn_ab_kernel(const float* __restrict__ X,
                   const float* __restrict__ Wa, const float* __restrict__ ba,
                   const float* __restrict__ Wb, const float* __restrict__ bbv) {
    __shared__ float xs[64][36];
    __shared__ float ws[32][33];
    const int tid  = threadIdx.x;
    const int row0 = blockIdx.x * 64;
    const int c    = tid & 31;
    const int rg   = tid >> 5;

    float acc[8];
    #pragma unroll
    for (int i = 0; i < 8; i++) acc[i] = 0.f;

    for (int k0 = 0; k0 < DD; k0 += 32) {
        __syncthreads();
        #pragma unroll
        for (int i = 0; i < 2; i++) {
            const int f = tid + i*256;
            const int r = f >> 3, c4 = (f & 7)*4;
            float4 val = *(const float4*)(X + (size_t)(row0 + r)*DD + k0 + c4);
            *(float4*)&xs[r][c4] = val;
        }
        #pragma unroll
        for (int i = 0; i < 4; i++) {
            const int f = tid + i*256;
            const int o = f >> 5, kkk = f & 31;
            const float* wr = (o < 16) ? (Wa + (size_t)o*DD) : (Wb + (size_t)(o - 16)*DD);
            ws[kkk][o] = wr[k0 + kkk];
        }
        __syncthreads();
        #pragma unroll 4
        for (int kkk = 0; kkk < 32; ++kkk) {
            const float w = ws[kkk][c];
            #pragma unroll
            for (int i = 0; i < 8; i++) acc[i] = fmaf(xs[rg*8 + i][kkk], w, acc[i]);
        }
    }

    #pragma unroll
    for (int i = 0; i < 8; i++) {
        const int bt = row0 + rg*8 + i;
        if (c < 16) {
            const float z = acc[i] + ba[c];
            g_alpha[(size_t)bt*HHN + c] = 1.f / (1.f + expf(-z));
        } else {
            const int h = c - 16;
            const float z = acc[i] + bbv[h];
            const float sp = fmaxf(z, 0.f) + log1pf(expf(-fabsf(z)));
            g_beta[(size_t)bt*HHN + h] = sp * 0.088388347648318447f;
        }
    }
}

// ---------------------------------------------------------------------------
// l2norm of q,k rows + fused kq[bt,h] = dot(q_norm, k_norm). Warp per row.
// ---------------------------------------------------------------------------
__global__ __launch_bounds__(256)
void gdn_l2norm_kernel() {
    const int gw   = (blockIdx.x * 256 + threadIdx.x) >> 5;
    const int lane = threadIdx.x & 31;

    float4* pq = reinterpret_cast<float4*>(g_q) + (size_t)gw*32 + lane;
    float4* pk = reinterpret_cast<float4*>(g_k) + (size_t)gw*32 + lane;
    float4 vq = *pq;
    float4 vk = *pk;

    float sq = vq.x*vq.x + vq.y*vq.y + vq.z*vq.z + vq.w*vq.w;
    float sk = vk.x*vk.x + vk.y*vk.y + vk.z*vk.z + vk.w*vk.w;
    #pragma unroll
    for (int o = 16; o; o >>= 1) {
        sq += __shfl_xor_sync(0xffffffffu, sq, o);
        sk += __shfl_xor_sync(0xffffffffu, sk, o);
    }
    const float iq = 1.0f / fmaxf(sqrtf(sq), 1e-12f);
    const float ik = 1.0f / fmaxf(sqrtf(sk), 1e-12f);
    vq.x *= iq; vq.y *= iq; vq.z *= iq; vq.w *= iq;
    vk.x *= ik; vk.y *= ik; vk.z *= ik; vk.w *= ik;
    *pq = vq;
    *pk = vk;

    float d = vq.x*vk.x + vq.y*vk.y + vq.z*vk.z + vq.w*vk.w;
    #pragma unroll
    for (int o = 16; o; o >>= 1) d += __shfl_xor_sync(0xffffffffu, d, o);
    if (lane == 0) g_kq[gw] = d;
}

// ---------------------------------------------------------------------------
// Pairwise cross-dots for 4-step groups. Warp per (b,h,g):
//   K_ij = k_i.k_j (i<j), X_ij = k_i.q_j (i<j), i,j in 1..4 within the group.
// Record layout matches scan's sequential-g reads. Runs AFTER l2norm.
// ---------------------------------------------------------------------------
__global__ __launch_bounds__(256)
void gdn_cross_kernel() {
    const int gw   = (blockIdx.x * 256 + threadIdx.x) >> 5;  // (b*HHN+h)*NG4+g
    const int lane = threadIdx.x & 31;
    const int g = gw & (NG4 - 1);
    const int h = (gw >> 9) & (HHN - 1);
    const int b = gw >> 13;
    const int t0 = 4 * g;

    const float4* kv[4];
    const float4* qv[4];
    #pragma unroll
    for (int i = 0; i < 4; i++) {
        kv[i] = (const float4*)(g_k + (size_t)(b*TT + t0 + i)*HK + h*KKD);
        qv[i] = (const float4*)(g_q + (size_t)(b*TT + t0 + i)*HK + h*KKD);
    }
    float4 k1 = kv[0][lane], k2 = kv[1][lane], k3 = kv[2][lane], k4 = kv[3][lane];
    float4 q2 = qv[1][lane], q3 = qv[2][lane], q4 = qv[3][lane];

    auto dot4 = [](float4 a, float4 b) {
        return a.x*b.x + a.y*b.y + a.z*b.z + a.w*b.w;
    };
    float dd[12];
    dd[0]  = dot4(k1, k2); dd[1]  = dot4(k1, k3); dd[2]  = dot4(k1, k4);
    dd[3]  = dot4(k2, k3); dd[4]  = dot4(k2, k4); dd[5]  = dot4(k3, k4);
    dd[6]  = dot4(k1, q2); dd[7]  = dot4(k1, q3); dd[8]  = dot4(k1, q4);
    dd[9]  = dot4(k2, q3); dd[10] = dot4(k2, q4); dd[11] = dot4(k3, q4);

    #pragma unroll
    for (int o = 16; o; o >>= 1)
        #pragma unroll
        for (int i = 0; i < 12; i++)
            dd[i] += __shfl_xor_sync(0xffffffffu, dd[i], o);

    if (lane == 0) {
        float* dst = g_cd + (size_t)gw * 12;
        *(float4*)(dst    ) = make_float4(dd[0], dd[1], dd[2],  dd[3]);
        *(float4*)(dst + 4) = make_float4(dd[4], dd[5], dd[6],  dd[7]);
        *(float4*)(dst + 8) = make_float4(dd[8], dd[9], dd[10], dd[11]);
    }
}

// ---------------------------------------------------------------------------
// Gated delta-rule scan v6: 4-step fused groups.
//  - CTA = 256 thr (8 warps) = 32 v-rows; grid (4,16,2) = 128 CTAs (1/SM).
//  - Per group: D_i = S.k_i, E_i = S.q_i (i=1..4) reduce CONCURRENTLY on
//    pre-update S: one 3-round shuffle cascade + one barrier per 4 steps.
//  - In-group propagation via precomputed pairwise dots (g_cd) + diag g_kq:
//      u_i = b_i (v_i - a_i s_{i-1}.k_i),  o_i = a_i s_{i-1}.q_i + u_i kq_i
//      s_{i-1}.x = a_{i-1}(...) + u_{i-1} <k_{i-1}, x>   (scalar chain)
//  - S update: S = (a1a2a3a4) S + (a2a3a4 u1) k1 + (a3a4 u2) k2 + (a4 u3) k3 + u4 k4
// ---------------------------------------------------------------------------
__device__ __forceinline__ ull f2fma(ull a, ull b, ull c) {
    ull d; asm("fma.rn.f32x2 %0, %1, %2, %3;" : "=l"(d) : "l"(a), "l"(b), "l"(c)); return d;
}
__device__ __forceinline__ ull f2mul(ull a, ull b) {
    ull d; asm("mul.rn.f32x2 %0, %1, %2;" : "=l"(d) : "l"(a), "l"(b)); return d;
}
__device__ __forceinline__ ull f2pack(float lo, float hi) {
    ull d; asm("mov.b64 %0, {%1, %2};" : "=l"(d) : "f"(lo), "f"(hi)); return d;
}
__device__ __forceinline__ float f2hsum(ull a) {
    float lo, hi; asm("mov.b64 {%0, %1}, %2;" : "=f"(lo), "=f"(hi) : "l"(a)); return lo + hi;
}

#define SLC 20   // floats per kg slice (16 data + 4 pad -> 80B stride)

__global__ __launch_bounds__(256, 1)
void gdn_scan_kernel(float* __restrict__ out) {
    __shared__ __align__(16) float kbuf[3][4][8*SLC];
    __shared__ __align__(16) float qbuf[3][4][8*SLC];

    const int b    = blockIdx.z;
    const int h    = blockIdx.y;
    const int tid  = threadIdx.x;
    const int w    = tid >> 5;
    const int lane = tid & 31;
    const int vi   = lane >> 3;        // 0..3
    const int kg   = lane & 7;         // 0..7 -> 16 k each
    const int vrow = blockIdx.x*32 + w*4 + vi;

    const float* krow = g_k     + (size_t)b*TT*HK + h*KKD;
    const float* qrow = g_q     + (size_t)b*TT*HK + h*KKD;
    const float* vp   = g_v     + (size_t)b*TT*HK + h*VVD + vrow;
    const float* ap   = g_alpha + (size_t)b*TT*HHN + h;
    const float* bp   = g_beta  + (size_t)b*TT*HHN + h;
    const float* kqp  = g_kq    + (size_t)b*TT*HHN + h;
    const float* cdp  = g_cd    + (size_t)(b*HHN + h)*NG4*12;
    float*       op   = out     + (size_t)b*TT*HK + h*VVD + vrow;

    // staging: 8 vectors (k1..k4,q1..q4) x 32 chunks = 256 -> 1 per thread
    const int vec = tid >> 5;          // 0..7
    const int sc  = tid & 31;

    auto stage = [&](int g, int s) {
        const float* src = ((vec < 4) ? krow : qrow) + (size_t)(4*g + (vec & 3))*HK + sc*4;
        float* dst = ((vec < 4) ? kbuf[s][vec & 3] : qbuf[s][vec & 3])
                     + (sc >> 2)*SLC + (sc & 3)*4;
        cp16(smem_u32(dst), src);
        CP_COMMIT();
    };

    stage(0, 0);
    stage(1, 1);

    ull S[8];
    #pragma unroll
    for (int i = 0; i < 8; i++) S[i] = 0;

    for (int g = 0; g < NG4; ++g) {
        asm volatile("cp.async.wait_group 1;" ::: "memory");
        __syncthreads();
        const int s = g % 3;
        if (g + 2 < NG4) stage(g + 2, (g + 2) % 3); else CP_COMMIT();

        // scalar loads issued early (used after reductions)
        const size_t t0 = (size_t)4*g;
        const float v1 = vp[t0*HK],      v2 = vp[(t0+1)*HK];
        const float v3 = vp[(t0+2)*HK],  v4 = vp[(t0+3)*HK];
        const float a1 = ap[t0*HHN],     a2 = ap[(t0+1)*HHN];
        const float a3 = ap[(t0+2)*HHN], a4 = ap[(t0+3)*HHN];
        const float b1 = bp[t0*HHN],     b2 = bp[(t0+1)*HHN];
        const float b3 = bp[(t0+2)*HHN], b4 = bp[(t0+3)*HHN];
        const float kq1 = kqp[t0*HHN],     kq2 = kqp[(t0+1)*HHN];
        const float kq3 = kqp[(t0+2)*HHN], kq4 = kqp[(t0+3)*HHN];
        const float4 cda = *(const float4*)(cdp + (size_t)g*12);
        const float4 cdb = *(const float4*)(cdp + (size_t)g*12 + 4);
        const float4 cdc = *(const float4*)(cdp + (size_t)g*12 + 8);
        // K12 K13 K14 K23 | K24 K34 X12 X13 | X14 X23 X24 X34
        const float K12 = cda.x, K13 = cda.y, K14 = cda.z, K23 = cda.w;
        const float K24 = cdb.x, K34 = cdb.y, X12 = cdb.z, X13 = cdb.w;
        const float X14 = cdc.x, X23 = cdc.y, X24 = cdc.z, X34 = cdc.w;

        // K vectors resident; Q streamed
        const ull* k1p = (const ull*)(kbuf[s][0] + kg*SLC);
        const ull* k2p = (const ull*)(kbuf[s][1] + kg*SLC);
        const ull* k3p = (const ull*)(kbuf[s][2] + kg*SLC);
        const ull* k4p = (const ull*)(kbuf[s][3] + kg*SLC);
        const ull* q1p = (const ull*)(qbuf[s][0] + kg*SLC);
        const ull* q2p = (const ull*)(qbuf[s][1] + kg*SLC);
        const ull* q3p = (const ull*)(qbuf[s][2] + kg*SLC);
        const ull* q4p = (const ull*)(qbuf[s][3] + kg*SLC);

        ull K1[8], K2[8], K3[8], K4[8];
        #pragma unroll
        for (int j = 0; j < 8; j++) {
            K1[j] = k1p[j]; K2[j] = k2p[j]; K3[j] = k3p[j]; K4[j] = k4p[j];
        }

        // 8 concurrent reductions on pre-update S
        ull d1 = f2mul(S[0], K1[0]), d2 = f2mul(S[0], K2[0]);
        ull d3 = f2mul(S[0], K3[0]), d4 = f2mul(S[0], K4[0]);
        ull e1 = f2mul(S[0], q1p[0]), e2 = f2mul(S[0], q2p[0]);
        ull e3 = f2mul(S[0], q3p[0]), e4 = f2mul(S[0], q4p[0]);
        #pragma unroll
        for (int j = 1; j < 8; j++) {
            d1 = f2fma(S[j], K1[j], d1); d2 = f2fma(S[j], K2[j], d2);
            d3 = f2fma(S[j], K3[j], d3); d4 = f2fma(S[j], K4[j], d4);
            e1 = f2fma(S[j], q1p[j], e1); e2 = f2fma(S[j], q2p[j], e2);
            e3 = f2fma(S[j], q3p[j], e3); e4 = f2fma(S[j], q4p[j], e4);
        }
        float D1 = f2hsum(d1), D2 = f2hsum(d2), D3 = f2hsum(d3), D4 = f2hsum(d4);
        float E1 = f2hsum(e1), E2 = f2hsum(e2), E3 = f2hsum(e3), E4 = f2hsum(e4);
        #pragma unroll
        for (int o = 1; o <= 4; o <<= 1) {
            D1 += __shfl_xor_sync(0xffffffffu, D1, o);
            D2 += __shfl_xor_sync(0xffffffffu, D2, o);
            D3 += __shfl_xor_sync(0xffffffffu, D3, o);
            D4 += __shfl_xor_sync(0xffffffffu, D4, o);
            E1 += __shfl_xor_sync(0xffffffffu, E1, o);
            E2 += __shfl_xor_sync(0xffffffffu, E2, o);
            E3 += __shfl_xor_sync(0xffffffffu, E3, o);
            E4 += __shfl_xor_sync(0xffffffffu, E4, o);
        }

        // scalar 4-step recurrence
        const float u1 = b1 * (v1 - a1 * D1);
        const float o1 = fmaf(u1, kq1, a1 * E1);
        const float s2k = fmaf(u1, K12, a1 * D2);
        const float u2  = b2 * (v2 - a2 * s2k);
        const float s2q = fmaf(u1, X12, a1 * E2);
        const float o2  = fmaf(u2, kq2, a2 * s2q);
        const float s3k = fmaf(u2, K23, a2 * fmaf(u1, K13, a1 * D3));
        const float u3  = b3 * (v3 - a3 * s3k);
        const float s3q = fmaf(u2, X23, a2 * fmaf(u1, X13, a1 * E3));
        const float o3  = fmaf(u3, kq3, a3 * s3q);
        const float s4k = fmaf(u3, K34, a3 * fmaf(u2, K24, a2 * fmaf(u1, K14, a1 * D4)));
        const float u4  = b4 * (v4 - a4 * s4k);
        const float s4q = fmaf(u3, X34, a3 * fmaf(u2, X24, a2 * fmaf(u1, X14, a1 * E4)));
        const float o4  = fmaf(u4, kq4, a4 * s4q);

        if (kg == 0) {
            op[(t0    )*HK] = o1;
            op[(t0 + 1)*HK] = o2;
            op[(t0 + 2)*HK] = o3;
            op[(t0 + 3)*HK] = o4;
        }

        // fused S update
        const float a43   = a4 * a3;
        const float a432  = a43 * a2;
        const float cS    = a432 * a1;
        const float ck1   = a432 * u1;
        const float ck2   = a43 * u2;
        const float ck3   = a4 * u3;
        const ull cS2  = f2pack(cS,  cS);
        const ull ck12 = f2pack(ck1, ck1);
        const ull ck22 = f2pack(ck2, ck2);
        const ull ck32 = f2pack(ck3, ck3);
        const ull ck42 = f2pack(u4,  u4);
        #pragma unroll
        for (int j = 0; j < 8; j++)
            S[j] = f2fma(ck42, K4[j],
                   f2fma(ck32, K3[j],
                   f2fma(ck22, K2[j],
                   f2fma(ck12, K1[j], f2mul(cS2, S[j])))));
    }
}

// ---------------------------------------------------------------------------
extern "C" void kernel_launch(void* const* d_in, const int* in_sizes, int n_in,
                              void* d_out, int out_size) {
    const float* x   = (const float*)d_in[0];
    const float* Wq  = (const float*)d_in[1];
    const float* Wk  = (const float*)d_in[2];
    const float* Wv  = (const float*)d_in[3];
    const float* Wa  = (const float*)d_in[4];
    const float* ba  = (const float*)d_in[5];
    const float* Wb  = (const float*)d_in[6];
    const float* bbv = (const float*)d_in[7];
    float* out = (float*)d_out;

    __half *xh, *wqh, *wkh, *wvh;
    cudaGetSymbolAddress((void**)&xh,  g_xh);
    cudaGetSymbolAddress((void**)&wqh, g_wqh);
    cudaGetSymbolAddress((void**)&wkh, g_wkh);
    cudaGetSymbolAddress((void**)&wvh, g_wvh);

    cudaFuncSetAttribute(gdn_proj_gemm, cudaFuncAttributeMaxDynamicSharedMemorySize, GEMM_SMEM);

    gdn_convh_kernel<<<1024, 256>>>(x,  (uint4*)xh,  BT*DD/8);
    gdn_convh_kernel<<<512,  256>>>(Wq, (uint4*)wqh, HK*DD/8);
    gdn_convh_kernel<<<512,  256>>>(Wk, (uint4*)wkh, HK*DD/8);
    gdn_convh_kernel<<<512,  256>>>(Wv, (uint4*)wvh, HK*DD/8);

    gdn_proj_gemm<<<dim3(HK/128, BT/128, 3), 256, GEMM_SMEM>>>();  // (16, 32, 3)
    gdn_ab_kernel<<<BT/64, 256>>>(x, Wa, ba, Wb, bbv);
    gdn_l2norm_kernel<<<(BT*HHN)/8, 256>>>();
    gdn_cross_kernel<<<(BB*HHN*NG4)/8, 256>>>();
    gdn_scan_kernel<<<dim3(4, HHN, BB), 256>>>(out);
}